// round 1
// baseline (speedup 1.0000x reference)
#include <cuda_runtime.h>
#include <cuda_bf16.h>
#include <math.h>

// Problem constants
#define Bz 4
#define Tz 512
#define Cz 768
#define Hz 12
#define Lz 8
#define Vz 512
#define FFz (4*Cz)
#define HDz (Cz/Hz)
#define Mz (Bz*Tz)
#define EPSz 1e-5f

// ---------------- scratch (device globals; no allocation allowed) -------------
__device__ float g_x [Mz*Cz];
__device__ float g_h [Mz*Cz];
__device__ float g_q [Mz*Cz];
__device__ float g_k [Mz*Cz];
__device__ float g_v [Mz*Cz];
__device__ float g_y [Mz*Cz];
__device__ float g_ff[Mz*FFz];

// ---------------- reductions ----------------
__device__ __forceinline__ float warp_sum(float v){
    #pragma unroll
    for (int o = 16; o; o >>= 1) v += __shfl_xor_sync(0xffffffffu, v, o);
    return v;
}
__device__ __forceinline__ float warp_max(float v){
    #pragma unroll
    for (int o = 16; o; o >>= 1) v = fmaxf(v, __shfl_xor_sync(0xffffffffu, v, o));
    return v;
}
// blockDim.x == 256 assumed (8 warps)
__device__ __forceinline__ float block_sum(float v, float* sh){
    __syncthreads();
    v = warp_sum(v);
    int w = threadIdx.x >> 5, l = threadIdx.x & 31;
    if (l == 0) sh[w] = v;
    __syncthreads();
    if (w == 0) {
        float t = (l < 8) ? sh[l] : 0.f;
        t = warp_sum(t);
        if (l == 0) sh[0] = t;
    }
    __syncthreads();
    return sh[0];
}
__device__ __forceinline__ float block_max(float v, float* sh){
    __syncthreads();
    v = warp_max(v);
    int w = threadIdx.x >> 5, l = threadIdx.x & 31;
    if (l == 0) sh[w] = v;
    __syncthreads();
    if (w == 0) {
        float t = (l < 8) ? sh[l] : -3.0e38f;
        t = warp_max(t);
        if (l == 0) sh[0] = t;
    }
    __syncthreads();
    return sh[0];
}

// ---------------- embeddings ----------------
__global__ void embed_k(const int* __restrict__ idx, const float* __restrict__ tok,
                        const float* __restrict__ typ, const float* __restrict__ pos,
                        float* __restrict__ x){
    int i = blockIdx.x * blockDim.x + threadIdx.x;
    if (i >= Mz*Cz) return;
    int c = i % Cz;
    int bt = i / Cz;
    int t = bt % Tz;
    x[i] = tok[(size_t)idx[bt]*Cz + c] + pos[(size_t)t*Cz + c] + typ[Cz + c];
}

// ---------------- layernorm (one block / row, 256 threads, C=768) ----------------
__global__ void ln_k(const float* __restrict__ in, const float* __restrict__ w,
                     const float* __restrict__ b, float* __restrict__ out){
    __shared__ float sh[8];
    int row = blockIdx.x;
    const float* xr = in + (size_t)row * Cz;
    float vals[3];
    float s = 0.f, s2 = 0.f;
    #pragma unroll
    for (int i = 0; i < 3; i++) {
        float v = xr[threadIdx.x + i*256];
        vals[i] = v; s += v; s2 += v*v;
    }
    float tot  = block_sum(s,  sh);
    float tot2 = block_sum(s2, sh);
    float mean = tot * (1.0f/Cz);
    float var  = tot2 * (1.0f/Cz) - mean*mean;
    float inv  = rsqrtf(var + EPSz);
    float* orow = out + (size_t)row * Cz;
    #pragma unroll
    for (int i = 0; i < 3; i++) {
        int c = threadIdx.x + i*256;
        orow[c] = (vals[i] - mean) * inv * w[c] + b[c];
    }
}

// ---------------- generic fp32 tiled GEMM ----------------
// C[M,N] = A[M,K] @ B (+bias[n]) (opt GELU) (+res[m,n])
// B is [K,N] row-major if !TRANSB, else [N,K] row-major.
// All dims: M%64==0, N%64==0, K%16==0 (true for every call here).
template<bool TRANSB, bool GELU>
__global__ void gemm_k(const float* __restrict__ A, const float* __restrict__ Bm,
                       const float* __restrict__ bias, const float* __restrict__ res,
                       float* __restrict__ Cm, int Mdim, int Ndim, int Kdim){
    __shared__ float As[64][17];
    __shared__ float Bs[16][64];
    int n0 = blockIdx.x * 64, m0 = blockIdx.y * 64;
    int tid = threadIdx.x;
    int tx = tid & 15, ty = tid >> 4;
    float acc[4][4] = {};
    for (int k0 = 0; k0 < Kdim; k0 += 16) {
        {   // load A tile: 64x16
            int m = tid >> 2, kq = (tid & 3) * 4;
            float4 a4 = *(const float4*)&A[(size_t)(m0+m)*Kdim + k0 + kq];
            As[m][kq+0] = a4.x; As[m][kq+1] = a4.y; As[m][kq+2] = a4.z; As[m][kq+3] = a4.w;
        }
        if (!TRANSB) {
            int kk = tid >> 4, nq = (tid & 15) * 4;
            float4 b4 = *(const float4*)&Bm[(size_t)(k0+kk)*Ndim + n0 + nq];
            *(float4*)&Bs[kk][nq] = b4;
        } else {
            int n = tid >> 2, kq = (tid & 3) * 4;
            float4 b4 = *(const float4*)&Bm[(size_t)(n0+n)*Kdim + k0 + kq];
            Bs[kq+0][n] = b4.x; Bs[kq+1][n] = b4.y; Bs[kq+2][n] = b4.z; Bs[kq+3][n] = b4.w;
        }
        __syncthreads();
        #pragma unroll
        for (int kk = 0; kk < 16; kk++) {
            float a[4];
            #pragma unroll
            for (int i = 0; i < 4; i++) a[i] = As[ty*4+i][kk];
            float4 b4 = *(float4*)&Bs[kk][tx*4];
            float bb[4] = {b4.x, b4.y, b4.z, b4.w};
            #pragma unroll
            for (int i = 0; i < 4; i++)
                #pragma unroll
                for (int j = 0; j < 4; j++)
                    acc[i][j] = fmaf(a[i], bb[j], acc[i][j]);
        }
        __syncthreads();
    }
    #pragma unroll
    for (int i = 0; i < 4; i++) {
        int m = m0 + ty*4 + i;
        #pragma unroll
        for (int j = 0; j < 4; j++) {
            int n = n0 + tx*4 + j;
            float v = acc[i][j];
            if (bias) v += bias[n];
            if (GELU) v = 0.5f * v * (1.0f + erff(v * 0.70710678118654752f));
            if (res)  v += res[(size_t)m*Ndim + n];
            Cm[(size_t)m*Ndim + n] = v;
        }
    }
}

// ---------------- attention scores + causal softmax ----------------
// grid: (T, B*H); block: 256. Writes directly to d_out attn region (layer base).
__global__ void attn_score_k(const float* __restrict__ q, const float* __restrict__ k,
                             float* __restrict__ att){
    __shared__ float qv[HDz];
    __shared__ float red[8];
    int qt = blockIdx.x;
    int bh = blockIdx.y;
    int b = bh / Hz, h = bh % Hz;
    const float* qp = q + ((size_t)(b*Tz + qt))*Cz + h*HDz;
    if (threadIdx.x < HDz) qv[threadIdx.x] = qp[threadIdx.x];
    __syncthreads();
    float sc[2];
    float mymax = -3.0e38f;
    #pragma unroll
    for (int i = 0; i < 2; i++) {
        int kt = threadIdx.x + i*256;
        float s = -3.0e38f;
        if (kt <= qt) {
            const float4* kp = (const float4*)(k + ((size_t)(b*Tz + kt))*Cz + h*HDz);
            float acc = 0.f;
            #pragma unroll
            for (int d4 = 0; d4 < HDz/4; d4++) {
                float4 kvv = kp[d4];
                acc = fmaf(qv[d4*4+0], kvv.x, acc);
                acc = fmaf(qv[d4*4+1], kvv.y, acc);
                acc = fmaf(qv[d4*4+2], kvv.z, acc);
                acc = fmaf(qv[d4*4+3], kvv.w, acc);
            }
            s = acc * 0.125f; // 1/sqrt(64)
        }
        sc[i] = s;
        mymax = fmaxf(mymax, s);
    }
    float m = block_max(mymax, red);
    float mysum = 0.f;
    #pragma unroll
    for (int i = 0; i < 2; i++) {
        int kt = threadIdx.x + i*256;
        float e = (kt <= qt) ? __expf(sc[i] - m) : 0.f;
        sc[i] = e;
        mysum += e;
    }
    float tot = block_sum(mysum, red);
    float inv = 1.0f / tot;
    float* ar = att + ((size_t)bh*Tz + qt)*Tz;
    ar[threadIdx.x]       = sc[0] * inv;
    ar[threadIdx.x + 256] = sc[1] * inv;
}

// ---------------- y = att @ v (batched over b,h), fused transpose-out ----------------
// grid: (M tiles = T/64, B*H); block 256. A: [T,T] lda=T, B: v slice ldb=C, C: y slice ldc=C
__global__ void attn_v_k(const float* __restrict__ att, const float* __restrict__ v,
                         float* __restrict__ y){
    __shared__ float As[64][17];
    __shared__ float Bs[16][64];
    int bh = blockIdx.y;
    int b = bh / Hz, h = bh % Hz;
    const float* Ap = att + (size_t)bh*Tz*Tz;
    const float* Bp = v + (size_t)b*Tz*Cz + h*HDz;
    float*       Cp = y + (size_t)b*Tz*Cz + h*HDz;
    int m0 = blockIdx.x * 64;
    int tid = threadIdx.x;
    int tx = tid & 15, ty = tid >> 4;
    float acc[4][4] = {};
    for (int k0 = 0; k0 < Tz; k0 += 16) {
        {
            int m = tid >> 2, kq = (tid & 3) * 4;
            float4 a4 = *(const float4*)&Ap[(size_t)(m0+m)*Tz + k0 + kq];
            As[m][kq+0] = a4.x; As[m][kq+1] = a4.y; As[m][kq+2] = a4.z; As[m][kq+3] = a4.w;
        }
        {
            int kk = tid >> 4, nq = (tid & 15) * 4;
            float4 b4 = *(const float4*)&Bp[(size_t)(k0+kk)*Cz + nq];
            *(float4*)&Bs[kk][nq] = b4;
        }
        __syncthreads();
        #pragma unroll
        for (int kk = 0; kk < 16; kk++) {
            float a[4];
            #pragma unroll
            for (int i = 0; i < 4; i++) a[i] = As[ty*4+i][kk];
            float4 b4 = *(float4*)&Bs[kk][tx*4];
            float bb[4] = {b4.x, b4.y, b4.z, b4.w};
            #pragma unroll
            for (int i = 0; i < 4; i++)
                #pragma unroll
                for (int j = 0; j < 4; j++)
                    acc[i][j] = fmaf(a[i], bb[j], acc[i][j]);
        }
        __syncthreads();
    }
    #pragma unroll
    for (int i = 0; i < 4; i++) {
        int m = m0 + ty*4 + i;
        #pragma unroll
        for (int j = 0; j < 4; j++) {
            Cp[(size_t)m*Cz + tx*4 + j] = acc[i][j];
        }
    }
}

// ---------------- host launch ----------------
extern "C" void kernel_launch(void* const* d_in, const int* in_sizes, int n_in,
                              void* d_out, int out_size){
    const int*   idx    = (const int*)  d_in[0];
    const float* tok    = (const float*)d_in[1];
    const float* typ    = (const float*)d_in[2];
    const float* pos    = (const float*)d_in[3];
    const float* Wq     = (const float*)d_in[4];
    const float* bq     = (const float*)d_in[5];
    const float* Wk     = (const float*)d_in[6];
    const float* bk     = (const float*)d_in[7];
    const float* Wv     = (const float*)d_in[8];
    const float* bv     = (const float*)d_in[9];
    const float* Wp     = (const float*)d_in[10];
    const float* bp     = (const float*)d_in[11];
    const float* ln1_w  = (const float*)d_in[12];
    const float* ln1_b  = (const float*)d_in[13];
    const float* ln2_w  = (const float*)d_in[14];
    const float* ln2_b  = (const float*)d_in[15];
    const float* W1     = (const float*)d_in[16];
    const float* b1     = (const float*)d_in[17];
    const float* W2     = (const float*)d_in[18];
    const float* b2     = (const float*)d_in[19];
    const float* lnf_w  = (const float*)d_in[20];
    const float* lnf_b  = (const float*)d_in[21];
    const float* head_w = (const float*)d_in[22];

    float* out        = (float*)d_out;
    float* out_logits = out;                                  // [B,T,V]
    float* out_x      = out + (size_t)Mz*Vz;                  // [B,T,C]
    float* out_att    = out_x + (size_t)Mz*Cz;                // [L,B,H,T,T]

    float *px, *ph, *pq, *pk, *pv, *py, *pff;
    cudaGetSymbolAddress((void**)&px,  g_x);
    cudaGetSymbolAddress((void**)&ph,  g_h);
    cudaGetSymbolAddress((void**)&pq,  g_q);
    cudaGetSymbolAddress((void**)&pk,  g_k);
    cudaGetSymbolAddress((void**)&pv,  g_v);
    cudaGetSymbolAddress((void**)&py,  g_y);
    cudaGetSymbolAddress((void**)&pff, g_ff);

    // embeddings
    embed_k<<<(Mz*Cz + 255)/256, 256>>>(idx, tok, typ, pos, px);

    dim3 gQKV(Cz/64, Mz/64);    // 12 x 32
    dim3 gFF1(FFz/64, Mz/64);   // 48 x 32
    dim3 gHead(Vz/64, Mz/64);   // 8 x 32
    dim3 gAtt(Tz, Bz*Hz);       // 512 x 48
    dim3 gAV(Tz/64, Bz*Hz);     // 8 x 48

    for (int l = 0; l < Lz; l++) {
        const float* wq = Wq + (size_t)l*Cz*Cz;
        const float* wk = Wk + (size_t)l*Cz*Cz;
        const float* wv = Wv + (size_t)l*Cz*Cz;
        const float* wp = Wp + (size_t)l*Cz*Cz;
        const float* w1 = W1 + (size_t)l*Cz*FFz;
        const float* w2 = W2 + (size_t)l*FFz*Cz;
        float* attL = out_att + (size_t)l*Bz*Hz*Tz*Tz;

        // LN1
        ln_k<<<Mz, 256>>>(px, ln1_w + (size_t)l*Cz, ln1_b + (size_t)l*Cz, ph);
        // QKV
        gemm_k<false,false><<<gQKV, 256>>>(ph, wq, bq + (size_t)l*Cz, nullptr, pq, Mz, Cz, Cz);
        gemm_k<false,false><<<gQKV, 256>>>(ph, wk, bk + (size_t)l*Cz, nullptr, pk, Mz, Cz, Cz);
        gemm_k<false,false><<<gQKV, 256>>>(ph, wv, bv + (size_t)l*Cz, nullptr, pv, Mz, Cz, Cz);
        // attention scores + softmax -> out attn region
        attn_score_k<<<gAtt, 256>>>(pq, pk, attL);
        // y = att @ v
        attn_v_k<<<gAV, 256>>>(attL, pv, py);
        // proj + residual: x = x + y@Wp + bp
        gemm_k<false,false><<<gQKV, 256>>>(py, wp, bp + (size_t)l*Cz, px, px, Mz, Cz, Cz);
        // LN2
        ln_k<<<Mz, 256>>>(px, ln2_w + (size_t)l*Cz, ln2_b + (size_t)l*Cz, ph);
        // FF1 + GELU
        gemm_k<false,true ><<<gFF1, 256>>>(ph, w1, b1 + (size_t)l*FFz, nullptr, pff, Mz, FFz, Cz);
        // FF2 + residual
        gemm_k<false,false><<<gQKV, 256>>>(pff, w2, b2 + (size_t)l*Cz, px, px, Mz, Cz, FFz);
    }

    // final LN -> out_x
    ln_k<<<Mz, 256>>>(px, lnf_w, lnf_b, out_x);
    // logits = out_x @ head_w^T
    gemm_k<true,false><<<gHead, 256>>>(out_x, head_w, nullptr, nullptr, out_logits, Mz, Vz, Cz);
}

// round 2
// speedup vs baseline: 1.7203x; 1.7203x over previous
#include <cuda_runtime.h>
#include <cuda_bf16.h>
#include <math.h>
#include <stdint.h>

// Problem constants
#define Bz 4
#define Tz 512
#define Cz 768
#define Hz 12
#define Lz 8
#define Vz 512
#define FFz (4*Cz)
#define HDz (Cz/Hz)
#define Mz (Bz*Tz)
#define EPSz 1e-5f

// ---------------- scratch (device globals; no allocation allowed) -------------
__device__ float g_x [Mz*Cz];
__device__ float g_h [Mz*Cz];
__device__ float g_q [Mz*Cz];
__device__ float g_k [Mz*Cz];
__device__ float g_v [Mz*Cz];
__device__ float g_y [Mz*Cz];
__device__ float g_ff[Mz*FFz];

// ---------------- reductions ----------------
__device__ __forceinline__ float warp_sum(float v){
    #pragma unroll
    for (int o = 16; o; o >>= 1) v += __shfl_xor_sync(0xffffffffu, v, o);
    return v;
}
__device__ __forceinline__ float warp_max(float v){
    #pragma unroll
    for (int o = 16; o; o >>= 1) v = fmaxf(v, __shfl_xor_sync(0xffffffffu, v, o));
    return v;
}
__device__ __forceinline__ float block_sum(float v, float* sh){
    __syncthreads();
    v = warp_sum(v);
    int w = threadIdx.x >> 5, l = threadIdx.x & 31;
    if (l == 0) sh[w] = v;
    __syncthreads();
    if (w == 0) {
        float t = (l < 8) ? sh[l] : 0.f;
        t = warp_sum(t);
        if (l == 0) sh[0] = t;
    }
    __syncthreads();
    return sh[0];
}
__device__ __forceinline__ float block_max(float v, float* sh){
    __syncthreads();
    v = warp_max(v);
    int w = threadIdx.x >> 5, l = threadIdx.x & 31;
    if (l == 0) sh[w] = v;
    __syncthreads();
    if (w == 0) {
        float t = (l < 8) ? sh[l] : -3.0e38f;
        t = warp_max(t);
        if (l == 0) sh[0] = t;
    }
    __syncthreads();
    return sh[0];
}

// ---------------- embeddings ----------------
__global__ void embed_k(const int* __restrict__ idx, const float* __restrict__ tok,
                        const float* __restrict__ typ, const float* __restrict__ pos,
                        float* __restrict__ x){
    int i = blockIdx.x * blockDim.x + threadIdx.x;
    if (i >= Mz*Cz) return;
    int c = i % Cz;
    int bt = i / Cz;
    int t = bt % Tz;
    x[i] = tok[(size_t)idx[bt]*Cz + c] + pos[(size_t)t*Cz + c] + typ[Cz + c];
}

// ---------------- layernorm (one block / row, 256 threads, C=768) ----------------
__global__ void ln_k(const float* __restrict__ in, const float* __restrict__ w,
                     const float* __restrict__ b, float* __restrict__ out){
    __shared__ float sh[8];
    int row = blockIdx.x;
    const float* xr = in + (size_t)row * Cz;
    float vals[3];
    float s = 0.f, s2 = 0.f;
    #pragma unroll
    for (int i = 0; i < 3; i++) {
        float v = xr[threadIdx.x + i*256];
        vals[i] = v; s += v; s2 += v*v;
    }
    float tot  = block_sum(s,  sh);
    float tot2 = block_sum(s2, sh);
    float mean = tot * (1.0f/Cz);
    float var  = tot2 * (1.0f/Cz) - mean*mean;
    float inv  = rsqrtf(var + EPSz);
    float* orow = out + (size_t)row * Cz;
    #pragma unroll
    for (int i = 0; i < 3; i++) {
        int c = threadIdx.x + i*256;
        orow[c] = (vals[i] - mean) * inv * w[c] + b[c];
    }
}

// ================= TF32 tensor-core GEMM =================
// C[M,N] = A[M,K] @ B[K,N] (+bias) (opt GELU) (+res)
// BM=128, BN=64, BK=32, 256 threads (8 warps, 4x2), warp tile 32x32,
// mma.sync.m16n8k8 tf32. Double-buffered smem with XOR swizzle
// (A: c ^ 4*(m&7), B: n ^ 8*(k&7)) -> conflict-free fragment loads.
#define BMt 128
#define BNt 64
#define BKt 32

__device__ __forceinline__ uint32_t f2tf(float f){
    uint32_t u; asm("cvt.rna.tf32.f32 %0, %1;" : "=r"(u) : "f"(f)); return u;
}

__device__ __forceinline__ void mma_tf32(float* d, const uint32_t* a, const uint32_t* b){
    asm volatile(
        "mma.sync.aligned.m16n8k8.row.col.f32.tf32.tf32.f32 "
        "{%0,%1,%2,%3}, {%4,%5,%6,%7}, {%8,%9}, {%0,%1,%2,%3};\n"
        : "+f"(d[0]), "+f"(d[1]), "+f"(d[2]), "+f"(d[3])
        : "r"(a[0]), "r"(a[1]), "r"(a[2]), "r"(a[3]), "r"(b[0]), "r"(b[1]));
}

template<bool GELU>
__global__ void __launch_bounds__(256, 2)
gemm_tf32_k(const float* __restrict__ A, const float* __restrict__ Bm,
            const float* __restrict__ bias, const float* __restrict__ res,
            float* __restrict__ Cm, int Mdim, int Ndim, int Kdim){
    __shared__ uint32_t As[2][BMt*BKt];
    __shared__ uint32_t Bs[2][BKt*BNt];
    const int tid  = threadIdx.x;
    const int lane = tid & 31;
    const int w    = tid >> 5;
    const int wm   = w >> 1;       // 0..3
    const int wn   = w & 1;        // 0..1
    const int m0   = blockIdx.y * BMt;
    const int n0   = blockIdx.x * BNt;
    const int gr   = lane >> 2;    // 0..7
    const int gc   = lane & 3;     // 0..3

    float acc[2][4][4];
    #pragma unroll
    for (int i = 0; i < 2; i++)
        #pragma unroll
        for (int j = 0; j < 4; j++)
            #pragma unroll
            for (int q = 0; q < 4; q++) acc[i][j][q] = 0.f;

    float4 ast[4];
    float4 bst[2];

    // staging index precompute
    const int am[4] = { (tid + 0*256) >> 3, (tid + 1*256) >> 3, (tid + 2*256) >> 3, (tid + 3*256) >> 3 };
    const int ak    = (tid & 7) << 2;
    const int bk_[2] = { (tid + 0*256) >> 4, (tid + 1*256) >> 4 };
    const int bn    = (tid & 15) << 2;

    #define LOAD_TILE(K0) do { \
        _Pragma("unroll") \
        for (int i = 0; i < 4; i++) \
            ast[i] = *(const float4*)&A[(size_t)(m0 + am[i])*Kdim + (K0) + ak]; \
        _Pragma("unroll") \
        for (int i = 0; i < 2; i++) \
            bst[i] = *(const float4*)&Bm[(size_t)((K0) + bk_[i])*Ndim + n0 + bn]; \
    } while(0)

    #define STORE_TILE(BUF) do { \
        _Pragma("unroll") \
        for (int i = 0; i < 4; i++) { \
            uint32_t* p = &As[BUF][am[i]*BKt + (ak ^ ((am[i] & 7) << 2))]; \
            *(uint4*)p = make_uint4(f2tf(ast[i].x), f2tf(ast[i].y), f2tf(ast[i].z), f2tf(ast[i].w)); \
        } \
        _Pragma("unroll") \
        for (int i = 0; i < 2; i++) { \
            uint32_t* p = &Bs[BUF][bk_[i]*BNt + (bn ^ ((bk_[i] & 7) << 3))]; \
            *(uint4*)p = make_uint4(f2tf(bst[i].x), f2tf(bst[i].y), f2tf(bst[i].z), f2tf(bst[i].w)); \
        } \
    } while(0)

    #define COMPUTE(BUF) do { \
        _Pragma("unroll") \
        for (int ks = 0; ks < 4; ks++) { \
            const int k8 = ks * 8; \
            uint32_t af[2][4]; \
            _Pragma("unroll") \
            for (int mt = 0; mt < 2; mt++) { \
                const int mr  = wm*32 + mt*16 + gr; \
                const int sw  = (mr & 7) << 2; \
                af[mt][0] = As[BUF][ mr     *BKt + ((k8 + gc    ) ^ sw)]; \
                af[mt][1] = As[BUF][(mr + 8)*BKt + ((k8 + gc    ) ^ sw)]; \
                af[mt][2] = As[BUF][ mr     *BKt + ((k8 + gc + 4) ^ sw)]; \
                af[mt][3] = As[BUF][(mr + 8)*BKt + ((k8 + gc + 4) ^ sw)]; \
            } \
            uint32_t bf[4][2]; \
            const int kk0 = k8 + gc, kk1 = k8 + gc + 4; \
            _Pragma("unroll") \
            for (int nt = 0; nt < 4; nt++) { \
                const int nc = wn*32 + nt*8 + gr; \
                bf[nt][0] = Bs[BUF][kk0*BNt + (nc ^ ((kk0 & 7) << 3))]; \
                bf[nt][1] = Bs[BUF][kk1*BNt + (nc ^ ((kk1 & 7) << 3))]; \
            } \
            _Pragma("unroll") \
            for (int mt = 0; mt < 2; mt++) \
                _Pragma("unroll") \
                for (int nt = 0; nt < 4; nt++) \
                    mma_tf32(acc[mt][nt], af[mt], bf[nt]); \
        } \
    } while(0)

    LOAD_TILE(0);
    STORE_TILE(0);
    __syncthreads();

    const int nk = Kdim / BKt;
    int buf = 0;
    for (int s = 1; s < nk; s++) {
        LOAD_TILE(s * BKt);
        COMPUTE(buf);
        STORE_TILE(buf ^ 1);
        __syncthreads();
        buf ^= 1;
    }
    COMPUTE(buf);

    // epilogue
    #pragma unroll
    for (int mt = 0; mt < 2; mt++) {
        #pragma unroll
        for (int nt = 0; nt < 4; nt++) {
            const int r0 = m0 + wm*32 + mt*16 + gr;
            const int c0 = n0 + wn*32 + nt*8 + gc*2;
            #pragma unroll
            for (int half = 0; half < 2; half++) {
                const int r = r0 + half*8;
                float v0 = acc[mt][nt][half*2 + 0];
                float v1 = acc[mt][nt][half*2 + 1];
                if (bias) { v0 += bias[c0]; v1 += bias[c0+1]; }
                if (GELU) {
                    v0 = 0.5f * v0 * (1.0f + erff(v0 * 0.70710678118654752f));
                    v1 = 0.5f * v1 * (1.0f + erff(v1 * 0.70710678118654752f));
                }
                if (res) {
                    v0 += res[(size_t)r*Ndim + c0];
                    v1 += res[(size_t)r*Ndim + c0 + 1];
                }
                *(float2*)&Cm[(size_t)r*Ndim + c0] = make_float2(v0, v1);
            }
        }
    }
    #undef LOAD_TILE
    #undef STORE_TILE
    #undef COMPUTE
}

// ---------------- fp32 SIMT GEMM (kept for head: B transposed) ----------------
template<bool TRANSB, bool GELU>
__global__ void gemm_k(const float* __restrict__ A, const float* __restrict__ Bm,
                       const float* __restrict__ bias, const float* __restrict__ res,
                       float* __restrict__ Cm, int Mdim, int Ndim, int Kdim){
    __shared__ float As[64][17];
    __shared__ float Bs[16][64];
    int n0 = blockIdx.x * 64, m0 = blockIdx.y * 64;
    int tid = threadIdx.x;
    int tx = tid & 15, ty = tid >> 4;
    float acc[4][4] = {};
    for (int k0 = 0; k0 < Kdim; k0 += 16) {
        {
            int m = tid >> 2, kq = (tid & 3) * 4;
            float4 a4 = *(const float4*)&A[(size_t)(m0+m)*Kdim + k0 + kq];
            As[m][kq+0] = a4.x; As[m][kq+1] = a4.y; As[m][kq+2] = a4.z; As[m][kq+3] = a4.w;
        }
        if (!TRANSB) {
            int kk = tid >> 4, nq = (tid & 15) * 4;
            float4 b4 = *(const float4*)&Bm[(size_t)(k0+kk)*Ndim + n0 + nq];
            *(float4*)&Bs[kk][nq] = b4;
        } else {
            int n = tid >> 2, kq = (tid & 3) * 4;
            float4 b4 = *(const float4*)&Bm[(size_t)(n0+n)*Kdim + k0 + kq];
            Bs[kq+0][n] = b4.x; Bs[kq+1][n] = b4.y; Bs[kq+2][n] = b4.z; Bs[kq+3][n] = b4.w;
        }
        __syncthreads();
        #pragma unroll
        for (int kk = 0; kk < 16; kk++) {
            float a[4];
            #pragma unroll
            for (int i = 0; i < 4; i++) a[i] = As[ty*4+i][kk];
            float4 b4 = *(float4*)&Bs[kk][tx*4];
            float bb[4] = {b4.x, b4.y, b4.z, b4.w};
            #pragma unroll
            for (int i = 0; i < 4; i++)
                #pragma unroll
                for (int j = 0; j < 4; j++)
                    acc[i][j] = fmaf(a[i], bb[j], acc[i][j]);
        }
        __syncthreads();
    }
    #pragma unroll
    for (int i = 0; i < 4; i++) {
        int m = m0 + ty*4 + i;
        #pragma unroll
        for (int j = 0; j < 4; j++) {
            int n = n0 + tx*4 + j;
            float v = acc[i][j];
            if (bias) v += bias[n];
            if (GELU) v = 0.5f * v * (1.0f + erff(v * 0.70710678118654752f));
            if (res)  v += res[(size_t)m*Ndim + n];
            Cm[(size_t)m*Ndim + n] = v;
        }
    }
}

// ---------------- attention scores + causal softmax ----------------
__global__ void attn_score_k(const float* __restrict__ q, const float* __restrict__ k,
                             float* __restrict__ att){
    __shared__ float qv[HDz];
    __shared__ float red[8];
    int qt = blockIdx.x;
    int bh = blockIdx.y;
    int b = bh / Hz, h = bh % Hz;
    const float* qp = q + ((size_t)(b*Tz + qt))*Cz + h*HDz;
    if (threadIdx.x < HDz) qv[threadIdx.x] = qp[threadIdx.x];
    __syncthreads();
    float sc[2];
    float mymax = -3.0e38f;
    #pragma unroll
    for (int i = 0; i < 2; i++) {
        int kt = threadIdx.x + i*256;
        float s = -3.0e38f;
        if (kt <= qt) {
            const float4* kp = (const float4*)(k + ((size_t)(b*Tz + kt))*Cz + h*HDz);
            float acc = 0.f;
            #pragma unroll
            for (int d4 = 0; d4 < HDz/4; d4++) {
                float4 kvv = kp[d4];
                acc = fmaf(qv[d4*4+0], kvv.x, acc);
                acc = fmaf(qv[d4*4+1], kvv.y, acc);
                acc = fmaf(qv[d4*4+2], kvv.z, acc);
                acc = fmaf(qv[d4*4+3], kvv.w, acc);
            }
            s = acc * 0.125f; // 1/sqrt(64)
        }
        sc[i] = s;
        mymax = fmaxf(mymax, s);
    }
    float m = block_max(mymax, red);
    float mysum = 0.f;
    #pragma unroll
    for (int i = 0; i < 2; i++) {
        int kt = threadIdx.x + i*256;
        float e = (kt <= qt) ? __expf(sc[i] - m) : 0.f;
        sc[i] = e;
        mysum += e;
    }
    float tot = block_sum(mysum, red);
    float inv = 1.0f / tot;
    float* ar = att + ((size_t)bh*Tz + qt)*Tz;
    ar[threadIdx.x]       = sc[0] * inv;
    ar[threadIdx.x + 256] = sc[1] * inv;
}

// ---------------- y = att @ v (batched over b,h), fused transpose-out ----------------
__global__ void attn_v_k(const float* __restrict__ att, const float* __restrict__ v,
                         float* __restrict__ y){
    __shared__ float As[64][17];
    __shared__ float Bs[16][64];
    int bh = blockIdx.y;
    int b = bh / Hz, h = bh % Hz;
    const float* Ap = att + (size_t)bh*Tz*Tz;
    const float* Bp = v + (size_t)b*Tz*Cz + h*HDz;
    float*       Cp = y + (size_t)b*Tz*Cz + h*HDz;
    int m0 = blockIdx.x * 64;
    int tid = threadIdx.x;
    int tx = tid & 15, ty = tid >> 4;
    float acc[4][4] = {};
    for (int k0 = 0; k0 < Tz; k0 += 16) {
        {
            int m = tid >> 2, kq = (tid & 3) * 4;
            float4 a4 = *(const float4*)&Ap[(size_t)(m0+m)*Tz + k0 + kq];
            As[m][kq+0] = a4.x; As[m][kq+1] = a4.y; As[m][kq+2] = a4.z; As[m][kq+3] = a4.w;
        }
        {
            int kk = tid >> 4, nq = (tid & 15) * 4;
            float4 b4 = *(const float4*)&Bp[(size_t)(k0+kk)*Cz + nq];
            *(float4*)&Bs[kk][nq] = b4;
        }
        __syncthreads();
        #pragma unroll
        for (int kk = 0; kk < 16; kk++) {
            float a[4];
            #pragma unroll
            for (int i = 0; i < 4; i++) a[i] = As[ty*4+i][kk];
            float4 b4 = *(float4*)&Bs[kk][tx*4];
            float bb[4] = {b4.x, b4.y, b4.z, b4.w};
            #pragma unroll
            for (int i = 0; i < 4; i++)
                #pragma unroll
                for (int j = 0; j < 4; j++)
                    acc[i][j] = fmaf(a[i], bb[j], acc[i][j]);
        }
        __syncthreads();
    }
    #pragma unroll
    for (int i = 0; i < 4; i++) {
        int m = m0 + ty*4 + i;
        #pragma unroll
        for (int j = 0; j < 4; j++) {
            Cp[(size_t)m*Cz + tx*4 + j] = acc[i][j];
        }
    }
}

// ---------------- host launch ----------------
extern "C" void kernel_launch(void* const* d_in, const int* in_sizes, int n_in,
                              void* d_out, int out_size){
    const int*   idx    = (const int*)  d_in[0];
    const float* tok    = (const float*)d_in[1];
    const float* typ    = (const float*)d_in[2];
    const float* pos    = (const float*)d_in[3];
    const float* Wq     = (const float*)d_in[4];
    const float* bq     = (const float*)d_in[5];
    const float* Wk     = (const float*)d_in[6];
    const float* bk     = (const float*)d_in[7];
    const float* Wv     = (const float*)d_in[8];
    const float* bv     = (const float*)d_in[9];
    const float* Wp     = (const float*)d_in[10];
    const float* bp     = (const float*)d_in[11];
    const float* ln1_w  = (const float*)d_in[12];
    const float* ln1_b  = (const float*)d_in[13];
    const float* ln2_w  = (const float*)d_in[14];
    const float* ln2_b  = (const float*)d_in[15];
    const float* W1     = (const float*)d_in[16];
    const float* b1     = (const float*)d_in[17];
    const float* W2     = (const float*)d_in[18];
    const float* b2     = (const float*)d_in[19];
    const float* lnf_w  = (const float*)d_in[20];
    const float* lnf_b  = (const float*)d_in[21];
    const float* head_w = (const float*)d_in[22];

    float* out        = (float*)d_out;
    float* out_logits = out;                                  // [B,T,V]
    float* out_x      = out + (size_t)Mz*Vz;                  // [B,T,C]
    float* out_att    = out_x + (size_t)Mz*Cz;                // [L,B,H,T,T]

    float *px, *ph, *pq, *pk, *pv, *py, *pff;
    cudaGetSymbolAddress((void**)&px,  g_x);
    cudaGetSymbolAddress((void**)&ph,  g_h);
    cudaGetSymbolAddress((void**)&pq,  g_q);
    cudaGetSymbolAddress((void**)&pk,  g_k);
    cudaGetSymbolAddress((void**)&pv,  g_v);
    cudaGetSymbolAddress((void**)&py,  g_y);
    cudaGetSymbolAddress((void**)&pff, g_ff);

    // embeddings
    embed_k<<<(Mz*Cz + 255)/256, 256>>>(idx, tok, typ, pos, px);

    dim3 gQKV(Cz/BNt,  Mz/BMt);   // 12 x 16
    dim3 gFF1(FFz/BNt, Mz/BMt);   // 48 x 16
    dim3 gHead(Vz/64, Mz/64);     // 8 x 32 (fp32 SIMT)
    dim3 gAtt(Tz, Bz*Hz);         // 512 x 48
    dim3 gAV(Tz/64, Bz*Hz);       // 8 x 48

    for (int l = 0; l < Lz; l++) {
        const float* wq = Wq + (size_t)l*Cz*Cz;
        const float* wk = Wk + (size_t)l*Cz*Cz;
        const float* wv = Wv + (size_t)l*Cz*Cz;
        const float* wp = Wp + (size_t)l*Cz*Cz;
        const float* w1 = W1 + (size_t)l*Cz*FFz;
        const float* w2 = W2 + (size_t)l*FFz*Cz;
        float* attL = out_att + (size_t)l*Bz*Hz*Tz*Tz;

        // LN1
        ln_k<<<Mz, 256>>>(px, ln1_w + (size_t)l*Cz, ln1_b + (size_t)l*Cz, ph);
        // QKV (tf32 tensor cores)
        gemm_tf32_k<false><<<gQKV, 256>>>(ph, wq, bq + (size_t)l*Cz, nullptr, pq, Mz, Cz, Cz);
        gemm_tf32_k<false><<<gQKV, 256>>>(ph, wk, bk + (size_t)l*Cz, nullptr, pk, Mz, Cz, Cz);
        gemm_tf32_k<false><<<gQKV, 256>>>(ph, wv, bv + (size_t)l*Cz, nullptr, pv, Mz, Cz, Cz);
        // attention scores + softmax -> out attn region
        attn_score_k<<<gAtt, 256>>>(pq, pk, attL);
        // y = att @ v
        attn_v_k<<<gAV, 256>>>(attL, pv, py);
        // proj + residual: x = x + y@Wp + bp
        gemm_tf32_k<false><<<gQKV, 256>>>(py, wp, bp + (size_t)l*Cz, px, px, Mz, Cz, Cz);
        // LN2
        ln_k<<<Mz, 256>>>(px, ln2_w + (size_t)l*Cz, ln2_b + (size_t)l*Cz, ph);
        // FF1 + GELU
        gemm_tf32_k<true ><<<gFF1, 256>>>(ph, w1, b1 + (size_t)l*FFz, nullptr, pff, Mz, FFz, Cz);
        // FF2 + residual
        gemm_tf32_k<false><<<gQKV, 256>>>(pff, w2, b2 + (size_t)l*Cz, px, px, Mz, Cz, FFz);
    }

    // final LN -> out_x
    ln_k<<<Mz, 256>>>(px, lnf_w, lnf_b, out_x);
    // logits = out_x @ head_w^T (fp32 for precision headroom)
    gemm_k<true,false><<<gHead, 256>>>(out_x, head_w, nullptr, nullptr, out_logits, Mz, Vz, Cz);
}

// round 3
// speedup vs baseline: 3.1218x; 1.8147x over previous
#include <cuda_runtime.h>
#include <cuda_bf16.h>
#include <math.h>
#include <stdint.h>

#define Bz 4
#define Tz 512
#define Cz 768
#define Hz 12
#define Lz 8
#define Vz 512
#define FFz (4*Cz)
#define HDz (Cz/Hz)
#define Mz (Bz*Tz)
#define EPSz 1e-5f

// ---------------- scratch ----------------
__device__ float g_x [Mz*Cz];
__device__ float g_h [Mz*Cz];
__device__ float g_q [Mz*Cz];
__device__ float g_k [Mz*Cz];
__device__ float g_v [Mz*Cz];
__device__ float g_y [Mz*Cz];
__device__ float g_ff[Mz*FFz];

// ---------------- warp reductions ----------------
__device__ __forceinline__ float warp_sum(float v){
    #pragma unroll
    for (int o = 16; o; o >>= 1) v += __shfl_xor_sync(0xffffffffu, v, o);
    return v;
}
__device__ __forceinline__ float warp_max(float v){
    #pragma unroll
    for (int o = 16; o; o >>= 1) v = fmaxf(v, __shfl_xor_sync(0xffffffffu, v, o));
    return v;
}

// ---------------- embeddings ----------------
__global__ void embed_k(const int* __restrict__ idx, const float* __restrict__ tok,
                        const float* __restrict__ typ, const float* __restrict__ pos,
                        float* __restrict__ x){
    int i = blockIdx.x * blockDim.x + threadIdx.x;
    if (i >= Mz*Cz) return;
    int c = i % Cz;
    int bt = i / Cz;
    int t = bt % Tz;
    x[i] = tok[(size_t)idx[bt]*Cz + c] + pos[(size_t)t*Cz + c] + typ[Cz + c];
}

// ---------------- layernorm: warp per row ----------------
__global__ void ln_k(const float* __restrict__ in, const float* __restrict__ w,
                     const float* __restrict__ b, float* __restrict__ out){
    int row = blockIdx.x*8 + (threadIdx.x >> 5);
    int lane = threadIdx.x & 31;
    const float* xr = in + (size_t)row * Cz;
    float v[24];
    float s = 0.f, s2 = 0.f;
    #pragma unroll
    for (int i = 0; i < 24; i++) {
        float t = xr[lane + i*32];
        v[i] = t; s += t; s2 += t*t;
    }
    s  = warp_sum(s);
    s2 = warp_sum(s2);
    float mean = s * (1.0f/Cz);
    float inv  = rsqrtf(s2 * (1.0f/Cz) - mean*mean + EPSz);
    float* orow = out + (size_t)row * Cz;
    #pragma unroll
    for (int i = 0; i < 24; i++) {
        int c = lane + i*32;
        orow[c] = (v[i] - mean) * inv * w[c] + b[c];
    }
}

// ================= TF32 tensor-core GEMM with cp.async pipeline =================
#define BMt 128
#define BNt 64
#define BKt 32
#define AS_SZ (BMt*BKt)   // 4096 u32
#define BS_SZ (BKt*BNt)   // 2048 u32
#define STAGES 3
#define GEMM_SMEM (STAGES*(AS_SZ+BS_SZ)*4)

__device__ __forceinline__ uint32_t f2tf(float f){
    uint32_t u; asm("cvt.rna.tf32.f32 %0, %1;" : "=r"(u) : "f"(f)); return u;
}
__device__ __forceinline__ void mma_tf32(float* d, const uint32_t* a, const uint32_t* b){
    asm volatile(
        "mma.sync.aligned.m16n8k8.row.col.f32.tf32.tf32.f32 "
        "{%0,%1,%2,%3}, {%4,%5,%6,%7}, {%8,%9}, {%0,%1,%2,%3};\n"
        : "+f"(d[0]), "+f"(d[1]), "+f"(d[2]), "+f"(d[3])
        : "r"(a[0]), "r"(a[1]), "r"(a[2]), "r"(a[3]), "r"(b[0]), "r"(b[1]));
}
__device__ __forceinline__ void cp16(uint32_t dst, const float* src){
    asm volatile("cp.async.cg.shared.global [%0], [%1], 16;" :: "r"(dst), "l"(src));
}
__device__ __forceinline__ void cp_commit(){ asm volatile("cp.async.commit_group;"); }
template<int N> __device__ __forceinline__ void cp_wait(){ asm volatile("cp.async.wait_group %0;" :: "n"(N)); }

template<bool GELU>
__device__ __forceinline__ void gemm_body(
    uint32_t* As, uint32_t* Bs,
    const float* __restrict__ A, const float* __restrict__ Bm,
    const float* __restrict__ bias, const float* __restrict__ res,
    float* __restrict__ Cm, int Ndim, int Kdim, int m0, int n0)
{
    const int tid  = threadIdx.x;
    const int lane = tid & 31;
    const int w    = tid >> 5;
    const int wm   = w >> 1;
    const int wn   = w & 1;
    const int gr   = lane >> 2;
    const int gc   = lane & 3;

    const int amr = tid >> 3;
    const int ak  = (tid & 7) << 2;
    const int bk0 = tid >> 4;
    const int bk1 = bk0 + 16;
    const int bn  = (tid & 15) << 2;

    uint32_t as_base = (uint32_t)__cvta_generic_to_shared(As);
    uint32_t bs_base = (uint32_t)__cvta_generic_to_shared(Bs);

    uint32_t adst[4], bdst[2];
    #pragma unroll
    for (int i = 0; i < 4; i++) {
        int m = amr + i*32;
        adst[i] = (uint32_t)(m*BKt + (ak ^ ((m & 7) << 2))) * 4u;
    }
    bdst[0] = (uint32_t)(bk0*BNt + (bn ^ ((bk0 & 7) << 3))) * 4u;
    bdst[1] = (uint32_t)(bk1*BNt + (bn ^ ((bk1 & 7) << 3))) * 4u;

    const int nk = Kdim / BKt;

    #define ISSUE(T) do { \
        int _buf = (T) % STAGES; int _k0 = (T) * BKt; \
        uint32_t _ab = as_base + (uint32_t)(_buf*AS_SZ*4); \
        uint32_t _bb = bs_base + (uint32_t)(_buf*BS_SZ*4); \
        _Pragma("unroll") \
        for (int i = 0; i < 4; i++) \
            cp16(_ab + adst[i], &A[(size_t)(m0 + amr + i*32)*Kdim + _k0 + ak]); \
        cp16(_bb + bdst[0], &Bm[(size_t)(_k0 + bk0)*Ndim + n0 + bn]); \
        cp16(_bb + bdst[1], &Bm[(size_t)(_k0 + bk1)*Ndim + n0 + bn]); \
    } while(0)

    float acc[2][4][4];
    #pragma unroll
    for (int i = 0; i < 2; i++)
        #pragma unroll
        for (int j = 0; j < 4; j++)
            #pragma unroll
            for (int q = 0; q < 4; q++) acc[i][j][q] = 0.f;

    ISSUE(0); cp_commit();
    ISSUE(1); cp_commit();

    for (int t = 0; t < nk; t++) {
        cp_wait<1>();
        __syncthreads();
        if (t + 2 < nk) ISSUE(t + 2);
        cp_commit();
        const uint32_t* as = As + (t % STAGES)*AS_SZ;
        const uint32_t* bs = Bs + (t % STAGES)*BS_SZ;
        #pragma unroll
        for (int ks = 0; ks < 4; ks++) {
            const int k8 = ks * 8;
            uint32_t af[2][4];
            #pragma unroll
            for (int mt = 0; mt < 2; mt++) {
                const int mr = wm*32 + mt*16 + gr;
                const int sw = (mr & 7) << 2;
                af[mt][0] = as[ mr     *BKt + ((k8 + gc    ) ^ sw)];
                af[mt][1] = as[(mr + 8)*BKt + ((k8 + gc    ) ^ sw)];
                af[mt][2] = as[ mr     *BKt + ((k8 + gc + 4) ^ sw)];
                af[mt][3] = as[(mr + 8)*BKt + ((k8 + gc + 4) ^ sw)];
                #pragma unroll
                for (int i = 0; i < 4; i++)
                    af[mt][i] = f2tf(__uint_as_float(af[mt][i]));
            }
            uint32_t bf[4][2];
            const int kk0 = k8 + gc, kk1 = k8 + gc + 4;
            #pragma unroll
            for (int nt = 0; nt < 4; nt++) {
                const int nc = wn*32 + nt*8 + gr;
                bf[nt][0] = f2tf(__uint_as_float(bs[kk0*BNt + (nc ^ ((kk0 & 7) << 3))]));
                bf[nt][1] = f2tf(__uint_as_float(bs[kk1*BNt + (nc ^ ((kk1 & 7) << 3))]));
            }
            #pragma unroll
            for (int mt = 0; mt < 2; mt++)
                #pragma unroll
                for (int nt = 0; nt < 4; nt++)
                    mma_tf32(acc[mt][nt], af[mt], bf[nt]);
        }
    }
    #undef ISSUE

    // epilogue
    #pragma unroll
    for (int mt = 0; mt < 2; mt++) {
        #pragma unroll
        for (int nt = 0; nt < 4; nt++) {
            const int r0 = m0 + wm*32 + mt*16 + gr;
            const int c0 = n0 + wn*32 + nt*8 + gc*2;
            #pragma unroll
            for (int half = 0; half < 2; half++) {
                const int r = r0 + half*8;
                float v0 = acc[mt][nt][half*2 + 0];
                float v1 = acc[mt][nt][half*2 + 1];
                if (bias) { v0 += bias[c0]; v1 += bias[c0+1]; }
                if (GELU) {
                    v0 = 0.5f * v0 * (1.0f + erff(v0 * 0.70710678118654752f));
                    v1 = 0.5f * v1 * (1.0f + erff(v1 * 0.70710678118654752f));
                }
                if (res) {
                    v0 += res[(size_t)r*Ndim + c0];
                    v1 += res[(size_t)r*Ndim + c0 + 1];
                }
                *(float2*)&Cm[(size_t)r*Ndim + c0] = make_float2(v0, v1);
            }
        }
    }
}

extern __shared__ unsigned char smem_raw[];

template<bool GELU>
__global__ void __launch_bounds__(256, 2)
gemm_tf32_k(const float* __restrict__ A, const float* __restrict__ Bm,
            const float* __restrict__ bias, const float* __restrict__ res,
            float* __restrict__ Cm, int Ndim, int Kdim){
    uint32_t* As = (uint32_t*)smem_raw;
    uint32_t* Bs = As + STAGES*AS_SZ;
    gemm_body<GELU>(As, Bs, A, Bm, bias, res, Cm, Ndim, Kdim,
                    blockIdx.y*BMt, blockIdx.x*BNt);
}

__global__ void __launch_bounds__(256, 2)
qkv_k(const float* __restrict__ h,
      const float* __restrict__ Wq, const float* __restrict__ Wk, const float* __restrict__ Wv,
      const float* __restrict__ bq, const float* __restrict__ bk, const float* __restrict__ bv,
      float* __restrict__ q, float* __restrict__ k, float* __restrict__ v){
    uint32_t* As = (uint32_t*)smem_raw;
    uint32_t* Bs = As + STAGES*AS_SZ;
    const float* W  = (blockIdx.z == 0) ? Wq : (blockIdx.z == 1) ? Wk : Wv;
    const float* bb = (blockIdx.z == 0) ? bq : (blockIdx.z == 1) ? bk : bv;
    float*       o  = (blockIdx.z == 0) ? q  : (blockIdx.z == 1) ? k  : v;
    gemm_body<false>(As, Bs, h, W, bb, nullptr, o, Cz, Cz,
                     blockIdx.y*BMt, blockIdx.x*BNt);
}

// ---------------- fp32 SIMT GEMM (head only, B transposed) ----------------
template<bool TRANSB>
__global__ void gemm_k(const float* __restrict__ A, const float* __restrict__ Bm,
                       float* __restrict__ Cm, int Ndim, int Kdim){
    __shared__ float As[64][17];
    __shared__ float Bs[16][64];
    int n0 = blockIdx.x * 64, m0 = blockIdx.y * 64;
    int tid = threadIdx.x;
    int tx = tid & 15, ty = tid >> 4;
    float acc[4][4] = {};
    for (int k0 = 0; k0 < Kdim; k0 += 16) {
        {
            int m = tid >> 2, kq = (tid & 3) * 4;
            float4 a4 = *(const float4*)&A[(size_t)(m0+m)*Kdim + k0 + kq];
            As[m][kq+0] = a4.x; As[m][kq+1] = a4.y; As[m][kq+2] = a4.z; As[m][kq+3] = a4.w;
        }
        {
            int n = tid >> 2, kq = (tid & 3) * 4;
            float4 b4 = *(const float4*)&Bm[(size_t)(n0+n)*Kdim + k0 + kq];
            Bs[kq+0][n] = b4.x; Bs[kq+1][n] = b4.y; Bs[kq+2][n] = b4.z; Bs[kq+3][n] = b4.w;
        }
        __syncthreads();
        #pragma unroll
        for (int kk = 0; kk < 16; kk++) {
            float a[4];
            #pragma unroll
            for (int i = 0; i < 4; i++) a[i] = As[ty*4+i][kk];
            float4 b4 = *(float4*)&Bs[kk][tx*4];
            float bb[4] = {b4.x, b4.y, b4.z, b4.w};
            #pragma unroll
            for (int i = 0; i < 4; i++)
                #pragma unroll
                for (int j = 0; j < 4; j++)
                    acc[i][j] = fmaf(a[i], bb[j], acc[i][j]);
        }
        __syncthreads();
    }
    #pragma unroll
    for (int i = 0; i < 4; i++) {
        int m = m0 + ty*4 + i;
        #pragma unroll
        for (int j = 0; j < 4; j++)
            Cm[(size_t)m*Ndim + n0 + tx*4 + j] = acc[i][j];
    }
}

// ---------------- attention scores + causal softmax (tiled, K-reuse) ----------------
// block: 64 q-rows x one (b,h). smem: S[64][512], Qs[64][68], Ks[64][64]
#define ATT_SMEM ((64*512 + 64*68 + 64*64)*4)
__global__ void __launch_bounds__(256, 1)
attn_score_k(const float* __restrict__ q, const float* __restrict__ k,
             float* __restrict__ att){
    float* S  = (float*)smem_raw;          // [64][512]
    float* Qs = S + 64*512;                // [64][68]  Qs[qi][d]
    float* Ks = Qs + 64*68;                // [64][64]  Ks[d][kt]
    const int q0 = blockIdx.x * 64;
    const int bh = blockIdx.y;
    const int b = bh / Hz, h = bh % Hz;
    const int tid = threadIdx.x;

    // load Q tile
    {
        int qi = tid >> 2;
        int d0 = (tid & 3) * 4;
        #pragma unroll
        for (int it = 0; it < 4; it++) {
            int d = d0 + it*16;
            float4 v = *(const float4*)&q[((size_t)(b*Tz + q0 + qi))*Cz + h*HDz + d];
            *(float4*)&Qs[qi*68 + d] = v;
        }
    }

    const int tx = tid & 15, ty = tid >> 4;
    const int kti = tid & 63;
    const int dq0 = (tid >> 6) * 4;
    const int ntiles = (q0 >> 6) + 1;

    for (int t = 0; t < ntiles; t++) {
        const int kt0 = t * 64;
        __syncthreads();
        // load K tile transposed: Ks[d][kt]
        #pragma unroll
        for (int it = 0; it < 4; it++) {
            int d = dq0 + it*16;
            float4 v = *(const float4*)&k[((size_t)(b*Tz + kt0 + kti))*Cz + h*HDz + d];
            Ks[(d+0)*64 + kti] = v.x;
            Ks[(d+1)*64 + kti] = v.y;
            Ks[(d+2)*64 + kti] = v.z;
            Ks[(d+3)*64 + kti] = v.w;
        }
        __syncthreads();
        float acc[4][4] = {};
        #pragma unroll 4
        for (int d = 0; d < HDz; d++) {
            float a[4];
            #pragma unroll
            for (int i = 0; i < 4; i++) a[i] = Qs[(ty*4+i)*68 + d];
            float4 b4 = *(float4*)&Ks[d*64 + tx*4];
            float bb[4] = {b4.x, b4.y, b4.z, b4.w};
            #pragma unroll
            for (int i = 0; i < 4; i++)
                #pragma unroll
                for (int j = 0; j < 4; j++)
                    acc[i][j] = fmaf(a[i], bb[j], acc[i][j]);
        }
        #pragma unroll
        for (int i = 0; i < 4; i++) {
            float4 o = make_float4(acc[i][0]*0.125f, acc[i][1]*0.125f,
                                   acc[i][2]*0.125f, acc[i][3]*0.125f);
            *(float4*)&S[(ty*4+i)*512 + kt0 + tx*4] = o;
        }
    }
    __syncthreads();

    // softmax: warp per row
    const int warp = tid >> 5, lane = tid & 31;
    const int kmax = q0 + 64;   // extent of computed region
    for (int r = warp; r < 64; r += 8) {
        const int qt = q0 + r;
        float mx = -3.0e38f;
        for (int kt = lane; kt < kmax; kt += 32) {
            float s = S[r*512 + kt];
            if (kt <= qt) mx = fmaxf(mx, s);
        }
        mx = warp_max(mx);
        float sum = 0.f;
        for (int kt = lane; kt < kmax; kt += 32) {
            float e = (kt <= qt) ? __expf(S[r*512 + kt] - mx) : 0.f;
            S[r*512 + kt] = e;
            sum += e;
        }
        sum = warp_sum(sum);
        float inv = 1.0f / sum;
        float* orow = att + ((size_t)bh*Tz + qt)*Tz;
        for (int kt = lane; kt < Tz; kt += 32)
            orow[kt] = (kt < kmax) ? S[r*512 + kt] * inv : 0.f;
    }
}

// ---------------- y = att @ v, causal k-bound, fused transpose-out ----------------
__global__ void attn_v_k(const float* __restrict__ att, const float* __restrict__ v,
                         float* __restrict__ y){
    __shared__ float As[64][17];
    __shared__ float Bs[16][64];
    int bh = blockIdx.y;
    int b = bh / Hz, h = bh % Hz;
    const float* Ap = att + (size_t)bh*Tz*Tz;
    const float* Bp = v + (size_t)b*Tz*Cz + h*HDz;
    float*       Cp = y + (size_t)b*Tz*Cz + h*HDz;
    int m0 = blockIdx.x * 64;
    int tid = threadIdx.x;
    int tx = tid & 15, ty = tid >> 4;
    float acc[4][4] = {};
    const int kend = m0 + 64;   // att[m][k]==0 for k>m
    for (int k0 = 0; k0 < kend; k0 += 16) {
        {
            int m = tid >> 2, kq = (tid & 3) * 4;
            float4 a4 = *(const float4*)&Ap[(size_t)(m0+m)*Tz + k0 + kq];
            As[m][kq+0] = a4.x; As[m][kq+1] = a4.y; As[m][kq+2] = a4.z; As[m][kq+3] = a4.w;
        }
        {
            int kk = tid >> 4, nq = (tid & 15) * 4;
            float4 b4 = *(const float4*)&Bp[(size_t)(k0+kk)*Cz + nq];
            *(float4*)&Bs[kk][nq] = b4;
        }
        __syncthreads();
        #pragma unroll
        for (int kk = 0; kk < 16; kk++) {
            float a[4];
            #pragma unroll
            for (int i = 0; i < 4; i++) a[i] = As[ty*4+i][kk];
            float4 b4 = *(float4*)&Bs[kk][tx*4];
            float bb[4] = {b4.x, b4.y, b4.z, b4.w};
            #pragma unroll
            for (int i = 0; i < 4; i++)
                #pragma unroll
                for (int j = 0; j < 4; j++)
                    acc[i][j] = fmaf(a[i], bb[j], acc[i][j]);
        }
        __syncthreads();
    }
    #pragma unroll
    for (int i = 0; i < 4; i++) {
        int m = m0 + ty*4 + i;
        #pragma unroll
        for (int j = 0; j < 4; j++)
            Cp[(size_t)m*Cz + tx*4 + j] = acc[i][j];
    }
}

// ---------------- host launch ----------------
extern "C" void kernel_launch(void* const* d_in, const int* in_sizes, int n_in,
                              void* d_out, int out_size){
    const int*   idx    = (const int*)  d_in[0];
    const float* tok    = (const float*)d_in[1];
    const float* typ    = (const float*)d_in[2];
    const float* pos    = (const float*)d_in[3];
    const float* Wq     = (const float*)d_in[4];
    const float* bq     = (const float*)d_in[5];
    const float* Wk     = (const float*)d_in[6];
    const float* bk     = (const float*)d_in[7];
    const float* Wv     = (const float*)d_in[8];
    const float* bv     = (const float*)d_in[9];
    const float* Wp     = (const float*)d_in[10];
    const float* bp     = (const float*)d_in[11];
    const float* ln1_w  = (const float*)d_in[12];
    const float* ln1_b  = (const float*)d_in[13];
    const float* ln2_w  = (const float*)d_in[14];
    const float* ln2_b  = (const float*)d_in[15];
    const float* W1     = (const float*)d_in[16];
    const float* b1     = (const float*)d_in[17];
    const float* W2     = (const float*)d_in[18];
    const float* b2     = (const float*)d_in[19];
    const float* lnf_w  = (const float*)d_in[20];
    const float* lnf_b  = (const float*)d_in[21];
    const float* head_w = (const float*)d_in[22];

    float* out        = (float*)d_out;
    float* out_logits = out;
    float* out_x      = out + (size_t)Mz*Vz;
    float* out_att    = out_x + (size_t)Mz*Cz;

    float *px, *ph, *pq, *pk, *pv, *py, *pff;
    cudaGetSymbolAddress((void**)&px,  g_x);
    cudaGetSymbolAddress((void**)&ph,  g_h);
    cudaGetSymbolAddress((void**)&pq,  g_q);
    cudaGetSymbolAddress((void**)&pk,  g_k);
    cudaGetSymbolAddress((void**)&pv,  g_v);
    cudaGetSymbolAddress((void**)&py,  g_y);
    cudaGetSymbolAddress((void**)&pff, g_ff);

    static bool attrs_set = false;
    if (!attrs_set) {
        cudaFuncSetAttribute((const void*)gemm_tf32_k<false>, cudaFuncAttributeMaxDynamicSharedMemorySize, GEMM_SMEM);
        cudaFuncSetAttribute((const void*)gemm_tf32_k<true>,  cudaFuncAttributeMaxDynamicSharedMemorySize, GEMM_SMEM);
        cudaFuncSetAttribute((const void*)qkv_k,              cudaFuncAttributeMaxDynamicSharedMemorySize, GEMM_SMEM);
        cudaFuncSetAttribute((const void*)attn_score_k,       cudaFuncAttributeMaxDynamicSharedMemorySize, ATT_SMEM);
        attrs_set = true;
    }

    embed_k<<<(Mz*Cz + 255)/256, 256>>>(idx, tok, typ, pos, px);

    dim3 gQKV3(Cz/BNt, Mz/BMt, 3);   // 12 x 16 x 3
    dim3 gP(Cz/BNt,  Mz/BMt);        // 12 x 16
    dim3 gFF1(FFz/BNt, Mz/BMt);      // 48 x 16
    dim3 gHead(Vz/64, Mz/64);        // 8 x 32
    dim3 gAtt(Tz/64, Bz*Hz);         // 8 x 48
    dim3 gAV(Tz/64, Bz*Hz);          // 8 x 48

    for (int l = 0; l < Lz; l++) {
        const float* wq = Wq + (size_t)l*Cz*Cz;
        const float* wk = Wk + (size_t)l*Cz*Cz;
        const float* wv = Wv + (size_t)l*Cz*Cz;
        const float* wp = Wp + (size_t)l*Cz*Cz;
        const float* w1 = W1 + (size_t)l*Cz*FFz;
        const float* w2 = W2 + (size_t)l*FFz*Cz;
        float* attL = out_att + (size_t)l*Bz*Hz*Tz*Tz;

        ln_k<<<Mz/8, 256>>>(px, ln1_w + (size_t)l*Cz, ln1_b + (size_t)l*Cz, ph);
        qkv_k<<<gQKV3, 256, GEMM_SMEM>>>(ph, wq, wk, wv,
                                         bq + (size_t)l*Cz, bk + (size_t)l*Cz, bv + (size_t)l*Cz,
                                         pq, pk, pv);
        attn_score_k<<<gAtt, 256, ATT_SMEM>>>(pq, pk, attL);
        attn_v_k<<<gAV, 256>>>(attL, pv, py);
        gemm_tf32_k<false><<<gP, 256, GEMM_SMEM>>>(py, wp, bp + (size_t)l*Cz, px, px, Cz, Cz);
        ln_k<<<Mz/8, 256>>>(px, ln2_w + (size_t)l*Cz, ln2_b + (size_t)l*Cz, ph);
        gemm_tf32_k<true ><<<gFF1, 256, GEMM_SMEM>>>(ph, w1, b1 + (size_t)l*FFz, nullptr, pff, FFz, Cz);
        gemm_tf32_k<false><<<gP, 256, GEMM_SMEM>>>(pff, w2, b2 + (size_t)l*Cz, px, px, Cz, FFz);
    }

    ln_k<<<Mz/8, 256>>>(px, lnf_w, lnf_b, out_x);
    gemm_k<true><<<gHead, 256>>>(out_x, head_w, out_logits, Vz, Cz);
}

// round 4
// speedup vs baseline: 3.6932x; 1.1830x over previous
#include <cuda_runtime.h>
#include <cuda_bf16.h>
#include <math.h>
#include <stdint.h>

#define Bz 4
#define Tz 512
#define Cz 768
#define Hz 12
#define Lz 8
#define Vz 512
#define FFz (4*Cz)
#define HDz (Cz/Hz)
#define Mz (Bz*Tz)
#define EPSz 1e-5f

// ---------------- scratch ----------------
__device__ float g_x [Mz*Cz];
__device__ float g_h [Mz*Cz];
__device__ float g_q [Mz*Cz];
__device__ float g_k [Mz*Cz];
__device__ float g_v [Mz*Cz];
__device__ float g_y [Mz*Cz];
__device__ float g_ff[Mz*FFz];

// ---------------- warp reductions ----------------
__device__ __forceinline__ float warp_sum(float v){
    #pragma unroll
    for (int o = 16; o; o >>= 1) v += __shfl_xor_sync(0xffffffffu, v, o);
    return v;
}
__device__ __forceinline__ float warp_max(float v){
    #pragma unroll
    for (int o = 16; o; o >>= 1) v = fmaxf(v, __shfl_xor_sync(0xffffffffu, v, o));
    return v;
}

// ---------------- embeddings ----------------
__global__ void embed_k(const int* __restrict__ idx, const float* __restrict__ tok,
                        const float* __restrict__ typ, const float* __restrict__ pos,
                        float* __restrict__ x){
    int i = blockIdx.x * blockDim.x + threadIdx.x;
    if (i >= Mz*Cz) return;
    int c = i % Cz;
    int bt = i / Cz;
    int t = bt % Tz;
    x[i] = tok[(size_t)idx[bt]*Cz + c] + pos[(size_t)t*Cz + c] + typ[Cz + c];
}

// ---------------- layernorm: warp per row ----------------
__global__ void ln_k(const float* __restrict__ in, const float* __restrict__ w,
                     const float* __restrict__ b, float* __restrict__ out){
    int row = blockIdx.x*8 + (threadIdx.x >> 5);
    int lane = threadIdx.x & 31;
    const float* xr = in + (size_t)row * Cz;
    float v[24];
    float s = 0.f, s2 = 0.f;
    #pragma unroll
    for (int i = 0; i < 24; i++) {
        float t = xr[lane + i*32];
        v[i] = t; s += t; s2 += t*t;
    }
    s  = warp_sum(s);
    s2 = warp_sum(s2);
    float mean = s * (1.0f/Cz);
    float inv  = rsqrtf(s2 * (1.0f/Cz) - mean*mean + EPSz);
    float* orow = out + (size_t)row * Cz;
    #pragma unroll
    for (int i = 0; i < 24; i++) {
        int c = lane + i*32;
        orow[c] = (v[i] - mean) * inv * w[c] + b[c];
    }
}

// ================= TF32 helpers =================
__device__ __forceinline__ uint32_t f2tf(float f){
    uint32_t u; asm("cvt.rna.tf32.f32 %0, %1;" : "=r"(u) : "f"(f)); return u;
}
__device__ __forceinline__ void mma_tf32(float* d, const uint32_t* a, const uint32_t* b){
    asm volatile(
        "mma.sync.aligned.m16n8k8.row.col.f32.tf32.tf32.f32 "
        "{%0,%1,%2,%3}, {%4,%5,%6,%7}, {%8,%9}, {%0,%1,%2,%3};\n"
        : "+f"(d[0]), "+f"(d[1]), "+f"(d[2]), "+f"(d[3])
        : "r"(a[0]), "r"(a[1]), "r"(a[2]), "r"(a[3]), "r"(b[0]), "r"(b[1]));
}
__device__ __forceinline__ void cp16(uint32_t dst, const float* src){
    asm volatile("cp.async.cg.shared.global [%0], [%1], 16;" :: "r"(dst), "l"(src));
}
__device__ __forceinline__ void cp_commit(){ asm volatile("cp.async.commit_group;"); }
template<int N> __device__ __forceinline__ void cp_wait(){ asm volatile("cp.async.wait_group %0;" :: "n"(N)); }

// ================= TF32 tensor-core GEMM, 4-stage cp.async =================
#define BMt 128
#define BNt 64
#define BKt 32
#define AS_SZ (BMt*BKt)
#define BS_SZ (BKt*BNt)
#define STAGES 4
#define GEMM_SMEM (STAGES*(AS_SZ+BS_SZ)*4)

template<bool GELU>
__device__ __forceinline__ void gemm_body(
    uint32_t* As, uint32_t* Bs,
    const float* __restrict__ A, const float* __restrict__ Bm,
    const float* __restrict__ bias, const float* __restrict__ res,
    float* __restrict__ Cm, int Ndim, int Kdim, int m0, int n0)
{
    const int tid  = threadIdx.x;
    const int lane = tid & 31;
    const int w    = tid >> 5;
    const int wm   = w >> 1;
    const int wn   = w & 1;
    const int gr   = lane >> 2;
    const int gc   = lane & 3;

    const int amr = tid >> 3;
    const int ak  = (tid & 7) << 2;
    const int bk0 = tid >> 4;
    const int bk1 = bk0 + 16;
    const int bn  = (tid & 15) << 2;

    uint32_t as_base = (uint32_t)__cvta_generic_to_shared(As);
    uint32_t bs_base = (uint32_t)__cvta_generic_to_shared(Bs);

    uint32_t adst[4], bdst[2];
    #pragma unroll
    for (int i = 0; i < 4; i++) {
        int m = amr + i*32;
        adst[i] = (uint32_t)(m*BKt + (ak ^ ((m & 7) << 2))) * 4u;
    }
    bdst[0] = (uint32_t)(bk0*BNt + (bn ^ ((bk0 & 7) << 3))) * 4u;
    bdst[1] = (uint32_t)(bk1*BNt + (bn ^ ((bk1 & 7) << 3))) * 4u;

    const int nk = Kdim / BKt;

    #define ISSUE(T) do { \
        int _buf = (T) % STAGES; int _k0 = (T) * BKt; \
        uint32_t _ab = as_base + (uint32_t)(_buf*AS_SZ*4); \
        uint32_t _bb = bs_base + (uint32_t)(_buf*BS_SZ*4); \
        _Pragma("unroll") \
        for (int i = 0; i < 4; i++) \
            cp16(_ab + adst[i], &A[(size_t)(m0 + amr + i*32)*Kdim + _k0 + ak]); \
        cp16(_bb + bdst[0], &Bm[(size_t)(_k0 + bk0)*Ndim + n0 + bn]); \
        cp16(_bb + bdst[1], &Bm[(size_t)(_k0 + bk1)*Ndim + n0 + bn]); \
    } while(0)

    float acc[2][4][4];
    #pragma unroll
    for (int i = 0; i < 2; i++)
        #pragma unroll
        for (int j = 0; j < 4; j++)
            #pragma unroll
            for (int q = 0; q < 4; q++) acc[i][j][q] = 0.f;

    ISSUE(0); cp_commit();
    ISSUE(1); cp_commit();
    ISSUE(2); cp_commit();

    for (int t = 0; t < nk; t++) {
        cp_wait<2>();
        __syncthreads();
        if (t + 3 < nk) ISSUE(t + 3);
        cp_commit();
        const uint32_t* as = As + (t % STAGES)*AS_SZ;
        const uint32_t* bs = Bs + (t % STAGES)*BS_SZ;
        #pragma unroll
        for (int ks = 0; ks < 4; ks++) {
            const int k8 = ks * 8;
            uint32_t af[2][4];
            #pragma unroll
            for (int mt = 0; mt < 2; mt++) {
                const int mr = wm*32 + mt*16 + gr;
                const int sw = (mr & 7) << 2;
                af[mt][0] = f2tf(__uint_as_float(as[ mr     *BKt + ((k8 + gc    ) ^ sw)]));
                af[mt][1] = f2tf(__uint_as_float(as[(mr + 8)*BKt + ((k8 + gc    ) ^ sw)]));
                af[mt][2] = f2tf(__uint_as_float(as[ mr     *BKt + ((k8 + gc + 4) ^ sw)]));
                af[mt][3] = f2tf(__uint_as_float(as[(mr + 8)*BKt + ((k8 + gc + 4) ^ sw)]));
            }
            uint32_t bf[4][2];
            const int kk0 = k8 + gc, kk1 = k8 + gc + 4;
            #pragma unroll
            for (int nt = 0; nt < 4; nt++) {
                const int nc = wn*32 + nt*8 + gr;
                bf[nt][0] = f2tf(__uint_as_float(bs[kk0*BNt + (nc ^ ((kk0 & 7) << 3))]));
                bf[nt][1] = f2tf(__uint_as_float(bs[kk1*BNt + (nc ^ ((kk1 & 7) << 3))]));
            }
            #pragma unroll
            for (int mt = 0; mt < 2; mt++)
                #pragma unroll
                for (int nt = 0; nt < 4; nt++)
                    mma_tf32(acc[mt][nt], af[mt], bf[nt]);
        }
    }
    #undef ISSUE

    #pragma unroll
    for (int mt = 0; mt < 2; mt++) {
        #pragma unroll
        for (int nt = 0; nt < 4; nt++) {
            const int r0 = m0 + wm*32 + mt*16 + gr;
            const int c0 = n0 + wn*32 + nt*8 + gc*2;
            #pragma unroll
            for (int half = 0; half < 2; half++) {
                const int r = r0 + half*8;
                float v0 = acc[mt][nt][half*2 + 0];
                float v1 = acc[mt][nt][half*2 + 1];
                if (bias) { v0 += bias[c0]; v1 += bias[c0+1]; }
                if (GELU) {
                    v0 = 0.5f * v0 * (1.0f + erff(v0 * 0.70710678118654752f));
                    v1 = 0.5f * v1 * (1.0f + erff(v1 * 0.70710678118654752f));
                }
                if (res) {
                    v0 += res[(size_t)r*Ndim + c0];
                    v1 += res[(size_t)r*Ndim + c0 + 1];
                }
                *(float2*)&Cm[(size_t)r*Ndim + c0] = make_float2(v0, v1);
            }
        }
    }
}

extern __shared__ unsigned char smem_raw[];

template<bool GELU>
__global__ void __launch_bounds__(256, 2)
gemm_tf32_k(const float* __restrict__ A, const float* __restrict__ Bm,
            const float* __restrict__ bias, const float* __restrict__ res,
            float* __restrict__ Cm, int Ndim, int Kdim){
    uint32_t* As = (uint32_t*)smem_raw;
    uint32_t* Bs = As + STAGES*AS_SZ;
    gemm_body<GELU>(As, Bs, A, Bm, bias, res, Cm, Ndim, Kdim,
                    blockIdx.y*BMt, blockIdx.x*BNt);
}

__global__ void __launch_bounds__(256, 2)
qkv_k(const float* __restrict__ h,
      const float* __restrict__ Wq, const float* __restrict__ Wk, const float* __restrict__ Wv,
      const float* __restrict__ bq, const float* __restrict__ bk, const float* __restrict__ bv,
      float* __restrict__ q, float* __restrict__ k, float* __restrict__ v){
    uint32_t* As = (uint32_t*)smem_raw;
    uint32_t* Bs = As + STAGES*AS_SZ;
    const float* W  = (blockIdx.z == 0) ? Wq : (blockIdx.z == 1) ? Wk : Wv;
    const float* bb = (blockIdx.z == 0) ? bq : (blockIdx.z == 1) ? bk : bv;
    float*       o  = (blockIdx.z == 0) ? q  : (blockIdx.z == 1) ? k  : v;
    gemm_body<false>(As, Bs, h, W, bb, nullptr, o, Cz, Cz,
                     blockIdx.y*BMt, blockIdx.x*BNt);
}

// ---------------- fp32 SIMT GEMM (head only, B transposed) ----------------
template<bool TRANSB>
__global__ void gemm_k(const float* __restrict__ A, const float* __restrict__ Bm,
                       float* __restrict__ Cm, int Ndim, int Kdim){
    __shared__ float As[64][17];
    __shared__ float Bs[16][64];
    int n0 = blockIdx.x * 64, m0 = blockIdx.y * 64;
    int tid = threadIdx.x;
    int tx = tid & 15, ty = tid >> 4;
    float acc[4][4] = {};
    for (int k0 = 0; k0 < Kdim; k0 += 16) {
        {
            int m = tid >> 2, kq = (tid & 3) * 4;
            float4 a4 = *(const float4*)&A[(size_t)(m0+m)*Kdim + k0 + kq];
            As[m][kq+0] = a4.x; As[m][kq+1] = a4.y; As[m][kq+2] = a4.z; As[m][kq+3] = a4.w;
        }
        {
            int n = tid >> 2, kq = (tid & 3) * 4;
            float4 b4 = *(const float4*)&Bm[(size_t)(n0+n)*Kdim + k0 + kq];
            Bs[kq+0][n] = b4.x; Bs[kq+1][n] = b4.y; Bs[kq+2][n] = b4.z; Bs[kq+3][n] = b4.w;
        }
        __syncthreads();
        #pragma unroll
        for (int kk = 0; kk < 16; kk++) {
            float a[4];
            #pragma unroll
            for (int i = 0; i < 4; i++) a[i] = As[ty*4+i][kk];
            float4 b4 = *(float4*)&Bs[kk][tx*4];
            float bb[4] = {b4.x, b4.y, b4.z, b4.w};
            #pragma unroll
            for (int i = 0; i < 4; i++)
                #pragma unroll
                for (int j = 0; j < 4; j++)
                    acc[i][j] = fmaf(a[i], bb[j], acc[i][j]);
        }
        __syncthreads();
    }
    #pragma unroll
    for (int i = 0; i < 4; i++) {
        int m = m0 + ty*4 + i;
        #pragma unroll
        for (int j = 0; j < 4; j++)
            Cm[(size_t)m*Ndim + n0 + tx*4 + j] = acc[i][j];
    }
}

// ============ fused attention: S = QK^T*scale, causal softmax, att out, y = P@V ============
// block: 64 q-rows x (b,h). 256 threads, 8 warps (2x4 warp grid, warp tile 32x16).
#define SST 516
#define ATTF_SMEM ((64*SST + 64*64 + 3*64*64)*4)

__global__ void __launch_bounds__(256, 1)
attn_fused_k(const float* __restrict__ q, const float* __restrict__ k,
             const float* __restrict__ v, float* __restrict__ att,
             float* __restrict__ y){
    float*    S  = (float*)smem_raw;            // [64][SST]
    uint32_t* Qs = (uint32_t*)(S + 64*SST);     // [64][64]
    uint32_t* Ks = Qs + 64*64;                  // 3 x [64][64]

    const int qb = gridDim.x - 1 - blockIdx.x;  // heavy blocks first
    const int q0 = qb * 64;
    const int bh = blockIdx.y;
    const int b = bh / Hz, h = bh % Hz;
    const int tid  = threadIdx.x;
    const int lane = tid & 31;
    const int w    = tid >> 5;
    const int wm   = w >> 2;      // 0..1
    const int wn   = w & 3;       // 0..3
    const int gr   = lane >> 2;
    const int gc   = lane & 3;
    const int ntiles = qb + 1;

    uint32_t qs_base = (uint32_t)__cvta_generic_to_shared(Qs);
    uint32_t ks_base = (uint32_t)__cvta_generic_to_shared(Ks);
    const int lrow = tid >> 2;        // 0..63
    const int lc0  = (tid & 3) * 4;   // 0,4,8,12

    #define ISSUE_KT(T) do { \
        uint32_t _kb = ks_base + (uint32_t)(((T) % 3) * 4096) * 4u; \
        _Pragma("unroll") \
        for (int it = 0; it < 4; it++) { \
            int c = lc0 + it*16; \
            cp16(_kb + (uint32_t)(lrow*64 + (c ^ ((lrow & 7) << 2)))*4u, \
                 &k[((size_t)(b*Tz + (T)*64 + lrow))*Cz + h*HDz + c]); \
        } \
    } while(0)

    // issue Q + K0
    #pragma unroll
    for (int it = 0; it < 4; it++) {
        int c = lc0 + it*16;
        cp16(qs_base + (uint32_t)(lrow*64 + (c ^ ((lrow & 7) << 2)))*4u,
             &q[((size_t)(b*Tz + q0 + lrow))*Cz + h*HDz + c]);
    }
    ISSUE_KT(0);
    cp_commit();
    if (ntiles > 1) ISSUE_KT(1);
    cp_commit();

    // -------- phase 1: scores --------
    for (int t = 0; t < ntiles; t++) {
        cp_wait<1>();
        __syncthreads();
        if (t + 2 < ntiles) ISSUE_KT(t + 2);
        cp_commit();
        const uint32_t* ks = Ks + (t % 3) * 4096;
        float acc[2][2][4];
        #pragma unroll
        for (int i = 0; i < 2; i++)
            #pragma unroll
            for (int j = 0; j < 2; j++)
                #pragma unroll
                for (int qq = 0; qq < 4; qq++) acc[i][j][qq] = 0.f;
        #pragma unroll
        for (int ks8 = 0; ks8 < 8; ks8++) {
            const int k8 = ks8 * 8;
            uint32_t af[2][4];
            #pragma unroll
            for (int mt = 0; mt < 2; mt++) {
                const int mr = wm*32 + mt*16 + gr;
                const int sw = (mr & 7) << 2;
                af[mt][0] = f2tf(__uint_as_float(Qs[ mr     *64 + ((k8 + gc    ) ^ sw)]));
                af[mt][1] = f2tf(__uint_as_float(Qs[(mr + 8)*64 + ((k8 + gc    ) ^ sw)]));
                af[mt][2] = f2tf(__uint_as_float(Qs[ mr     *64 + ((k8 + gc + 4) ^ sw)]));
                af[mt][3] = f2tf(__uint_as_float(Qs[(mr + 8)*64 + ((k8 + gc + 4) ^ sw)]));
            }
            uint32_t bf[2][2];
            #pragma unroll
            for (int nt = 0; nt < 2; nt++) {
                const int nr = wn*16 + nt*8 + gr;
                const int sw = (nr & 7) << 2;
                bf[nt][0] = f2tf(__uint_as_float(ks[nr*64 + ((k8 + gc    ) ^ sw)]));
                bf[nt][1] = f2tf(__uint_as_float(ks[nr*64 + ((k8 + gc + 4) ^ sw)]));
            }
            #pragma unroll
            for (int mt = 0; mt < 2; mt++)
                #pragma unroll
                for (int nt = 0; nt < 2; nt++)
                    mma_tf32(acc[mt][nt], af[mt], bf[nt]);
        }
        const int kt0 = t * 64;
        #pragma unroll
        for (int mt = 0; mt < 2; mt++) {
            #pragma unroll
            for (int nt = 0; nt < 2; nt++) {
                const int r = wm*32 + mt*16 + gr;
                const int c = kt0 + wn*16 + nt*8 + gc*2;
                *(float2*)&S[ r     *SST + c] = make_float2(acc[mt][nt][0]*0.125f, acc[mt][nt][1]*0.125f);
                *(float2*)&S[(r + 8)*SST + c] = make_float2(acc[mt][nt][2]*0.125f, acc[mt][nt][3]*0.125f);
            }
        }
    }
    __syncthreads();

    // -------- softmax (warp per row), normalize in S, write att --------
    const int kmax = q0 + 64;
    for (int r = w; r < 64; r += 8) {
        const int qt = q0 + r;
        float* Sr = &S[r*SST];
        float mx = -3.0e38f;
        for (int kt = lane; kt < kmax; kt += 32) {
            float s = Sr[kt];
            if (kt <= qt) mx = fmaxf(mx, s);
        }
        mx = warp_max(mx);
        float sum = 0.f;
        for (int kt = lane; kt < kmax; kt += 32) {
            float e = (kt <= qt) ? __expf(Sr[kt] - mx) : 0.f;
            Sr[kt] = e;
            sum += e;
        }
        sum = warp_sum(sum);
        const float inv = 1.0f / sum;
        float* orow = att + ((size_t)bh*Tz + qt)*Tz;
        for (int kt = lane; kt < kmax; kt += 32) {
            float p = Sr[kt] * inv;
            Sr[kt] = p;
            orow[kt] = p;
        }
        for (int kt = kmax + lane; kt < Tz; kt += 32) orow[kt] = 0.f;
    }
    __syncthreads();

    // -------- phase 2: y = P @ V --------
    uint32_t* Vs = Ks;           // reuse buffer 0: [d][kt] transposed, tf32
    const int kti = tid & 63;
    const int dg  = (tid >> 6) * 4;
    float4 vreg[4];
    #pragma unroll
    for (int it = 0; it < 4; it++)
        vreg[it] = *(const float4*)&v[((size_t)(b*Tz + kti))*Cz + h*HDz + dg + it*16];

    float acc2[2][2][4];
    #pragma unroll
    for (int i = 0; i < 2; i++)
        #pragma unroll
        for (int j = 0; j < 2; j++)
            #pragma unroll
            for (int qq = 0; qq < 4; qq++) acc2[i][j][qq] = 0.f;

    for (int t = 0; t < ntiles; t++) {
        __syncthreads();    // previous compute done reading Vs
        #pragma unroll
        for (int it = 0; it < 4; it++) {
            const int d0 = dg + it*16;
            const float4 vv = vreg[it];
            Vs[(d0+0)*64 + (kti ^ (((d0+0) & 7) << 2))] = f2tf(vv.x);
            Vs[(d0+1)*64 + (kti ^ (((d0+1) & 7) << 2))] = f2tf(vv.y);
            Vs[(d0+2)*64 + (kti ^ (((d0+2) & 7) << 2))] = f2tf(vv.z);
            Vs[(d0+3)*64 + (kti ^ (((d0+3) & 7) << 2))] = f2tf(vv.w);
        }
        if (t + 1 < ntiles) {
            #pragma unroll
            for (int it = 0; it < 4; it++)
                vreg[it] = *(const float4*)&v[((size_t)(b*Tz + (t+1)*64 + kti))*Cz + h*HDz + dg + it*16];
        }
        __syncthreads();
        const int kt0 = t * 64;
        #pragma unroll
        for (int ks8 = 0; ks8 < 8; ks8++) {
            const int k8 = ks8 * 8;
            uint32_t af[2][4];
            #pragma unroll
            for (int mt = 0; mt < 2; mt++) {
                const int mr = wm*32 + mt*16 + gr;
                af[mt][0] = f2tf(S[ mr     *SST + kt0 + k8 + gc    ]);
                af[mt][1] = f2tf(S[(mr + 8)*SST + kt0 + k8 + gc    ]);
                af[mt][2] = f2tf(S[ mr     *SST + kt0 + k8 + gc + 4]);
                af[mt][3] = f2tf(S[(mr + 8)*SST + kt0 + k8 + gc + 4]);
            }
            uint32_t bf[2][2];
            #pragma unroll
            for (int nt = 0; nt < 2; nt++) {
                const int nr = wn*16 + nt*8 + gr;
                const int sw = (nr & 7) << 2;
                bf[nt][0] = Vs[nr*64 + ((k8 + gc    ) ^ sw)];
                bf[nt][1] = Vs[nr*64 + ((k8 + gc + 4) ^ sw)];
            }
            #pragma unroll
            for (int mt = 0; mt < 2; mt++)
                #pragma unroll
                for (int nt = 0; nt < 2; nt++)
                    mma_tf32(acc2[mt][nt], af[mt], bf[nt]);
        }
    }

    // write y (fused transpose to [B,T,C])
    float* Cp = y + ((size_t)(b*Tz + q0))*Cz + h*HDz;
    #pragma unroll
    for (int mt = 0; mt < 2; mt++) {
        #pragma unroll
        for (int nt = 0; nt < 2; nt++) {
            const int r = wm*32 + mt*16 + gr;
            const int c = wn*16 + nt*8 + gc*2;
            *(float2*)&Cp[(size_t) r     *Cz + c] = make_float2(acc2[mt][nt][0], acc2[mt][nt][1]);
            *(float2*)&Cp[(size_t)(r + 8)*Cz + c] = make_float2(acc2[mt][nt][2], acc2[mt][nt][3]);
        }
    }
    #undef ISSUE_KT
}

// ---------------- host launch ----------------
extern "C" void kernel_launch(void* const* d_in, const int* in_sizes, int n_in,
                              void* d_out, int out_size){
    const int*   idx    = (const int*)  d_in[0];
    const float* tok    = (const float*)d_in[1];
    const float* typ    = (const float*)d_in[2];
    const float* pos    = (const float*)d_in[3];
    const float* Wq     = (const float*)d_in[4];
    const float* bq     = (const float*)d_in[5];
    const float* Wk     = (const float*)d_in[6];
    const float* bk     = (const float*)d_in[7];
    const float* Wv     = (const float*)d_in[8];
    const float* bv     = (const float*)d_in[9];
    const float* Wp     = (const float*)d_in[10];
    const float* bp     = (const float*)d_in[11];
    const float* ln1_w  = (const float*)d_in[12];
    const float* ln1_b  = (const float*)d_in[13];
    const float* ln2_w  = (const float*)d_in[14];
    const float* ln2_b  = (const float*)d_in[15];
    const float* W1     = (const float*)d_in[16];
    const float* b1     = (const float*)d_in[17];
    const float* W2     = (const float*)d_in[18];
    const float* b2     = (const float*)d_in[19];
    const float* lnf_w  = (const float*)d_in[20];
    const float* lnf_b  = (const float*)d_in[21];
    const float* head_w = (const float*)d_in[22];

    float* out        = (float*)d_out;
    float* out_logits = out;
    float* out_x      = out + (size_t)Mz*Vz;
    float* out_att    = out_x + (size_t)Mz*Cz;

    float *px, *ph, *pq, *pk, *pv, *py, *pff;
    cudaGetSymbolAddress((void**)&px,  g_x);
    cudaGetSymbolAddress((void**)&ph,  g_h);
    cudaGetSymbolAddress((void**)&pq,  g_q);
    cudaGetSymbolAddress((void**)&pk,  g_k);
    cudaGetSymbolAddress((void**)&pv,  g_v);
    cudaGetSymbolAddress((void**)&py,  g_y);
    cudaGetSymbolAddress((void**)&pff, g_ff);

    static bool attrs_set = false;
    if (!attrs_set) {
        cudaFuncSetAttribute((const void*)gemm_tf32_k<false>, cudaFuncAttributeMaxDynamicSharedMemorySize, GEMM_SMEM);
        cudaFuncSetAttribute((const void*)gemm_tf32_k<true>,  cudaFuncAttributeMaxDynamicSharedMemorySize, GEMM_SMEM);
        cudaFuncSetAttribute((const void*)qkv_k,              cudaFuncAttributeMaxDynamicSharedMemorySize, GEMM_SMEM);
        cudaFuncSetAttribute((const void*)attn_fused_k,       cudaFuncAttributeMaxDynamicSharedMemorySize, ATTF_SMEM);
        attrs_set = true;
    }

    embed_k<<<(Mz*Cz + 255)/256, 256>>>(idx, tok, typ, pos, px);

    dim3 gQKV3(Cz/BNt, Mz/BMt, 3);
    dim3 gP(Cz/BNt,  Mz/BMt);
    dim3 gFF1(FFz/BNt, Mz/BMt);
    dim3 gHead(Vz/64, Mz/64);
    dim3 gAtt(Tz/64, Bz*Hz);

    for (int l = 0; l < Lz; l++) {
        const float* wq = Wq + (size_t)l*Cz*Cz;
        const float* wk = Wk + (size_t)l*Cz*Cz;
        const float* wv = Wv + (size_t)l*Cz*Cz;
        const float* wp = Wp + (size_t)l*Cz*Cz;
        const float* w1 = W1 + (size_t)l*Cz*FFz;
        const float* w2 = W2 + (size_t)l*FFz*Cz;
        float* attL = out_att + (size_t)l*Bz*Hz*Tz*Tz;

        ln_k<<<Mz/8, 256>>>(px, ln1_w + (size_t)l*Cz, ln1_b + (size_t)l*Cz, ph);
        qkv_k<<<gQKV3, 256, GEMM_SMEM>>>(ph, wq, wk, wv,
                                         bq + (size_t)l*Cz, bk + (size_t)l*Cz, bv + (size_t)l*Cz,
                                         pq, pk, pv);
        attn_fused_k<<<gAtt, 256, ATTF_SMEM>>>(pq, pk, pv, attL, py);
        gemm_tf32_k<false><<<gP, 256, GEMM_SMEM>>>(py, wp, bp + (size_t)l*Cz, px, px, Cz, Cz);
        ln_k<<<Mz/8, 256>>>(px, ln2_w + (size_t)l*Cz, ln2_b + (size_t)l*Cz, ph);
        gemm_tf32_k<true ><<<gFF1, 256, GEMM_SMEM>>>(ph, w1, b1 + (size_t)l*FFz, nullptr, pff, FFz, Cz);
        gemm_tf32_k<false><<<gP, 256, GEMM_SMEM>>>(pff, w2, b2 + (size_t)l*Cz, px, px, Cz, FFz);
    }

    ln_k<<<Mz/8, 256>>>(px, lnf_w, lnf_b, out_x);
    gemm_k<true><<<gHead, 256>>>(out_x, head_w, out_logits, Vz, Cz);
}

// round 5
// speedup vs baseline: 4.0665x; 1.1011x over previous
#include <cuda_runtime.h>
#include <cuda_bf16.h>
#include <math.h>
#include <stdint.h>

#define Bz 4
#define Tz 512
#define Cz 768
#define Hz 12
#define Lz 8
#define Vz 512
#define FFz (4*Cz)
#define HDz (Cz/Hz)
#define Mz (Bz*Tz)
#define EPSz 1e-5f

// ---------------- scratch ----------------
__device__ float g_x [Mz*Cz];
__device__ float g_h [Mz*Cz];
__device__ float g_q [Mz*Cz];
__device__ float g_k [Mz*Cz];
__device__ float g_v [Mz*Cz];
__device__ float g_y [Mz*Cz];
__device__ float g_ff[Mz*FFz];
// transposed + tf32-prerounded weights: [N][K] layout
__device__ float g_wq[Lz*Cz*Cz];
__device__ float g_wk[Lz*Cz*Cz];
__device__ float g_wv[Lz*Cz*Cz];
__device__ float g_wp[Lz*Cz*Cz];
__device__ float g_w1[Lz*Cz*FFz];   // [FF][C] per layer
__device__ float g_w2[Lz*FFz*Cz];   // [C][FF] per layer

// ---------------- warp reductions ----------------
__device__ __forceinline__ float warp_sum(float v){
    #pragma unroll
    for (int o = 16; o; o >>= 1) v += __shfl_xor_sync(0xffffffffu, v, o);
    return v;
}
__device__ __forceinline__ float warp_max(float v){
    #pragma unroll
    for (int o = 16; o; o >>= 1) v = fmaxf(v, __shfl_xor_sync(0xffffffffu, v, o));
    return v;
}

// ================= TF32 / mma / cp.async helpers =================
__device__ __forceinline__ uint32_t f2tf(float f){
    uint32_t u; asm("cvt.rna.tf32.f32 %0, %1;" : "=r"(u) : "f"(f)); return u;
}
__device__ __forceinline__ float roundtf(float f){ return __uint_as_float(f2tf(f)); }
__device__ __forceinline__ void mma_tf32(float* d, const uint32_t* a, const uint32_t* b){
    asm volatile(
        "mma.sync.aligned.m16n8k8.row.col.f32.tf32.tf32.f32 "
        "{%0,%1,%2,%3}, {%4,%5,%6,%7}, {%8,%9}, {%0,%1,%2,%3};\n"
        : "+f"(d[0]), "+f"(d[1]), "+f"(d[2]), "+f"(d[3])
        : "r"(a[0]), "r"(a[1]), "r"(a[2]), "r"(a[3]), "r"(b[0]), "r"(b[1]));
}
__device__ __forceinline__ void ldsm4(uint32_t* r, uint32_t addr){
    asm volatile("ldmatrix.sync.aligned.m8n8.x4.shared.b16 {%0,%1,%2,%3}, [%4];"
        : "=r"(r[0]), "=r"(r[1]), "=r"(r[2]), "=r"(r[3]) : "r"(addr));
}
__device__ __forceinline__ void cp16(uint32_t dst, const float* src){
    asm volatile("cp.async.cg.shared.global [%0], [%1], 16;" :: "r"(dst), "l"(src));
}
__device__ __forceinline__ void cp_commit(){ asm volatile("cp.async.commit_group;"); }
template<int N> __device__ __forceinline__ void cp_wait(){ asm volatile("cp.async.wait_group %0;" :: "n"(N)); }

// ---------------- embeddings ----------------
__global__ void embed_k(const int* __restrict__ idx, const float* __restrict__ tok,
                        const float* __restrict__ typ, const float* __restrict__ pos,
                        float* __restrict__ x){
    int i = blockIdx.x * blockDim.x + threadIdx.x;
    if (i >= Mz*Cz) return;
    int c = i % Cz;
    int bt = i / Cz;
    int t = bt % Tz;
    x[i] = tok[(size_t)idx[bt]*Cz + c] + pos[(size_t)t*Cz + c] + typ[Cz + c];
}

// ---------------- weight transpose + tf32 pre-round: src[K,N] -> dst[N,K] ----------------
__global__ void wtrans_k(const float* __restrict__ src, float* __restrict__ dst,
                         int K, int N){
    __shared__ float tile[32][33];
    const size_t mat = (size_t)blockIdx.z * (size_t)K * N;
    src += mat; dst += mat;
    int n0 = blockIdx.x*32, k0 = blockIdx.y*32;
    #pragma unroll
    for (int i = threadIdx.y; i < 32; i += 8)
        tile[i][threadIdx.x] = src[(size_t)(k0+i)*N + n0 + threadIdx.x];
    __syncthreads();
    #pragma unroll
    for (int i = threadIdx.y; i < 32; i += 8)
        dst[(size_t)(n0+i)*K + k0 + threadIdx.x] = roundtf(tile[threadIdx.x][i]);
}

// ---------------- layernorm: warp per row ----------------
template<bool ROUND>
__global__ void ln_k(const float* __restrict__ in, const float* __restrict__ w,
                     const float* __restrict__ b, float* __restrict__ out){
    int row = blockIdx.x*8 + (threadIdx.x >> 5);
    int lane = threadIdx.x & 31;
    const float* xr = in + (size_t)row * Cz;
    float v[24];
    float s = 0.f, s2 = 0.f;
    #pragma unroll
    for (int i = 0; i < 24; i++) {
        float t = xr[lane + i*32];
        v[i] = t; s += t; s2 += t*t;
    }
    s  = warp_sum(s);
    s2 = warp_sum(s2);
    float mean = s * (1.0f/Cz);
    float inv  = rsqrtf(s2 * (1.0f/Cz) - mean*mean + EPSz);
    float* orow = out + (size_t)row * Cz;
    #pragma unroll
    for (int i = 0; i < 24; i++) {
        int c = lane + i*32;
        float o = (v[i] - mean) * inv * w[c] + b[c];
        orow[c] = ROUND ? roundtf(o) : o;
    }
}

// ================= TF32 tensor-core GEMM: ldmatrix both operands, 4-stage =================
// A[M,K] fp32 (pre-rounded to tf32 values), Bt[N,K] tf32-prerounded.
#define BMt 128
#define BNt 64
#define BKt 32
#define AS_SZ (BMt*BKt)
#define BS_SZ (BNt*BKt)
#define STAGES 4
#define GEMM_SMEM (STAGES*(AS_SZ+BS_SZ)*4)

template<bool GELU, bool ROUND>
__device__ __forceinline__ void gemm_body(
    uint32_t* As, uint32_t* Bs,
    const float* __restrict__ A, const float* __restrict__ Bt,
    const float* __restrict__ bias, const float* __restrict__ res,
    float* __restrict__ Cm, int Ndim, int Kdim, int m0, int n0)
{
    const int tid  = threadIdx.x;
    const int lane = tid & 31;
    const int w    = tid >> 5;
    const int wm   = w >> 1;      // 0..3
    const int wn   = w & 1;       // 0..1
    const int gr   = lane >> 2;
    const int gc   = lane & 3;

    // staging (both tiles are rows x 32 floats)
    const int amr = tid >> 3;           // 0..31
    const int ak  = (tid & 7) << 2;

    uint32_t as_base = (uint32_t)__cvta_generic_to_shared(As);
    uint32_t bs_base = (uint32_t)__cvta_generic_to_shared(Bs);

    uint32_t adst[4], bdst[2];
    #pragma unroll
    for (int i = 0; i < 4; i++) {
        int m = amr + i*32;
        adst[i] = (uint32_t)(m*BKt + (ak ^ ((m & 7) << 2))) * 4u;
    }
    #pragma unroll
    for (int j = 0; j < 2; j++) {
        int n = amr + j*32;
        bdst[j] = (uint32_t)(n*BKt + (ak ^ ((n & 7) << 2))) * 4u;
    }

    const int nk = Kdim / BKt;

    #define ISSUE(T) do { \
        int _buf = (T) % STAGES; int _k0 = (T) * BKt; \
        uint32_t _ab = as_base + (uint32_t)(_buf*AS_SZ*4); \
        uint32_t _bb = bs_base + (uint32_t)(_buf*BS_SZ*4); \
        _Pragma("unroll") \
        for (int i = 0; i < 4; i++) \
            cp16(_ab + adst[i], &A[(size_t)(m0 + amr + i*32)*Kdim + _k0 + ak]); \
        _Pragma("unroll") \
        for (int j = 0; j < 2; j++) \
            cp16(_bb + bdst[j], &Bt[(size_t)(n0 + amr + j*32)*Kdim + _k0 + ak]); \
    } while(0)

    // fragment ldmatrix lane roles
    const int a_s4 = (lane >> 4) << 2;   // 0 or 4
    const int b_s4 = (lane >> 3) << 2;   // 0,4,8,12
    int a_m[2], b_n[4];
    #pragma unroll
    for (int mt = 0; mt < 2; mt++) a_m[mt] = wm*32 + mt*16 + (lane & 15);
    #pragma unroll
    for (int nt = 0; nt < 4; nt++) b_n[nt] = wn*32 + nt*8 + (lane & 7);

    float acc[2][4][4];
    #pragma unroll
    for (int i = 0; i < 2; i++)
        #pragma unroll
        for (int j = 0; j < 4; j++)
            #pragma unroll
            for (int q = 0; q < 4; q++) acc[i][j][q] = 0.f;

    ISSUE(0); cp_commit();
    ISSUE(1); cp_commit();
    ISSUE(2); cp_commit();

    for (int t = 0; t < nk; t++) {
        cp_wait<2>();
        __syncthreads();
        if (t + 3 < nk) ISSUE(t + 3);
        cp_commit();
        const uint32_t ab = as_base + (uint32_t)((t % STAGES)*AS_SZ*4);
        const uint32_t bb = bs_base + (uint32_t)((t % STAGES)*BS_SZ*4);

        uint32_t breg[4][8];
        #pragma unroll
        for (int nt = 0; nt < 4; nt++) {
            const int nr = b_n[nt];
            const int sw = (nr & 7) << 2;
            ldsm4(&breg[nt][0], bb + (uint32_t)(nr*BKt + ((0  + b_s4) ^ sw))*4u);
            ldsm4(&breg[nt][4], bb + (uint32_t)(nr*BKt + ((16 + b_s4) ^ sw))*4u);
        }
        #pragma unroll
        for (int ks = 0; ks < 4; ks++) {
            const int k8 = ks * 8;
            uint32_t areg[2][4];
            #pragma unroll
            for (int mt = 0; mt < 2; mt++) {
                const int mr = a_m[mt];
                const int sw = (mr & 7) << 2;
                ldsm4(areg[mt], ab + (uint32_t)(mr*BKt + ((k8 + a_s4) ^ sw))*4u);
            }
            #pragma unroll
            for (int mt = 0; mt < 2; mt++)
                #pragma unroll
                for (int nt = 0; nt < 4; nt++)
                    mma_tf32(acc[mt][nt], areg[mt], &breg[nt][ks*2]);
        }
    }
    #undef ISSUE

    #pragma unroll
    for (int mt = 0; mt < 2; mt++) {
        #pragma unroll
        for (int nt = 0; nt < 4; nt++) {
            const int r0 = m0 + wm*32 + mt*16 + gr;
            const int c0 = n0 + wn*32 + nt*8 + gc*2;
            #pragma unroll
            for (int half = 0; half < 2; half++) {
                const int r = r0 + half*8;
                float v0 = acc[mt][nt][half*2 + 0];
                float v1 = acc[mt][nt][half*2 + 1];
                if (bias) { v0 += bias[c0]; v1 += bias[c0+1]; }
                if (GELU) {
                    v0 = 0.5f * v0 * (1.0f + erff(v0 * 0.70710678118654752f));
                    v1 = 0.5f * v1 * (1.0f + erff(v1 * 0.70710678118654752f));
                }
                if (res) {
                    v0 += res[(size_t)r*Ndim + c0];
                    v1 += res[(size_t)r*Ndim + c0 + 1];
                }
                if (ROUND) { v0 = roundtf(v0); v1 = roundtf(v1); }
                *(float2*)&Cm[(size_t)r*Ndim + c0] = make_float2(v0, v1);
            }
        }
    }
}

extern __shared__ unsigned char smem_raw[];

template<bool GELU, bool ROUND>
__global__ void __launch_bounds__(256, 2)
gemm_tf32_k(const float* __restrict__ A, const float* __restrict__ Bt,
            const float* __restrict__ bias, const float* __restrict__ res,
            float* __restrict__ Cm, int Ndim, int Kdim){
    uint32_t* As = (uint32_t*)smem_raw;
    uint32_t* Bs = As + STAGES*AS_SZ;
    gemm_body<GELU, ROUND>(As, Bs, A, Bt, bias, res, Cm, Ndim, Kdim,
                           blockIdx.y*BMt, blockIdx.x*BNt);
}

__global__ void __launch_bounds__(256, 2)
qkv_k(const float* __restrict__ h,
      const float* __restrict__ Wq, const float* __restrict__ Wk, const float* __restrict__ Wv,
      const float* __restrict__ bq, const float* __restrict__ bk, const float* __restrict__ bv,
      float* __restrict__ q, float* __restrict__ k, float* __restrict__ v){
    uint32_t* As = (uint32_t*)smem_raw;
    uint32_t* Bs = As + STAGES*AS_SZ;
    const float* W  = (blockIdx.z == 0) ? Wq : (blockIdx.z == 1) ? Wk : Wv;
    const float* bb = (blockIdx.z == 0) ? bq : (blockIdx.z == 1) ? bk : bv;
    float*       o  = (blockIdx.z == 0) ? q  : (blockIdx.z == 1) ? k  : v;
    gemm_body<false, true>(As, Bs, h, W, bb, nullptr, o, Cz, Cz,
                           blockIdx.y*BMt, blockIdx.x*BNt);
}

// ---------------- fp32 SIMT GEMM (head only, B transposed) ----------------
__global__ void gemm_head_k(const float* __restrict__ A, const float* __restrict__ Bm,
                            float* __restrict__ Cm, int Ndim, int Kdim){
    __shared__ float As[64][17];
    __shared__ float Bs[16][64];
    int n0 = blockIdx.x * 64, m0 = blockIdx.y * 64;
    int tid = threadIdx.x;
    int tx = tid & 15, ty = tid >> 4;
    float acc[4][4] = {};
    for (int k0 = 0; k0 < Kdim; k0 += 16) {
        {
            int m = tid >> 2, kq = (tid & 3) * 4;
            float4 a4 = *(const float4*)&A[(size_t)(m0+m)*Kdim + k0 + kq];
            As[m][kq+0] = a4.x; As[m][kq+1] = a4.y; As[m][kq+2] = a4.z; As[m][kq+3] = a4.w;
        }
        {
            int n = tid >> 2, kq = (tid & 3) * 4;
            float4 b4 = *(const float4*)&Bm[(size_t)(n0+n)*Kdim + k0 + kq];
            Bs[kq+0][n] = b4.x; Bs[kq+1][n] = b4.y; Bs[kq+2][n] = b4.z; Bs[kq+3][n] = b4.w;
        }
        __syncthreads();
        #pragma unroll
        for (int kk = 0; kk < 16; kk++) {
            float a[4];
            #pragma unroll
            for (int i = 0; i < 4; i++) a[i] = As[ty*4+i][kk];
            float4 b4 = *(float4*)&Bs[kk][tx*4];
            float bb[4] = {b4.x, b4.y, b4.z, b4.w};
            #pragma unroll
            for (int i = 0; i < 4; i++)
                #pragma unroll
                for (int j = 0; j < 4; j++)
                    acc[i][j] = fmaf(a[i], bb[j], acc[i][j]);
        }
        __syncthreads();
    }
    #pragma unroll
    for (int i = 0; i < 4; i++) {
        int m = m0 + ty*4 + i;
        #pragma unroll
        for (int j = 0; j < 4; j++)
            Cm[(size_t)m*Ndim + n0 + tx*4 + j] = acc[i][j];
    }
}

// ============ fused attention (unchanged except y rounded) ============
#define SST 516
#define ATTF_SMEM ((64*SST + 64*64 + 3*64*64)*4)

__global__ void __launch_bounds__(256, 1)
attn_fused_k(const float* __restrict__ q, const float* __restrict__ k,
             const float* __restrict__ v, float* __restrict__ att,
             float* __restrict__ y){
    float*    S  = (float*)smem_raw;
    uint32_t* Qs = (uint32_t*)(S + 64*SST);
    uint32_t* Ks = Qs + 64*64;

    const int qb = gridDim.x - 1 - blockIdx.x;
    const int q0 = qb * 64;
    const int bh = blockIdx.y;
    const int b = bh / Hz, h = bh % Hz;
    const int tid  = threadIdx.x;
    const int lane = tid & 31;
    const int w    = tid >> 5;
    const int wm   = w >> 2;
    const int wn   = w & 3;
    const int gr   = lane >> 2;
    const int gc   = lane & 3;
    const int ntiles = qb + 1;

    uint32_t qs_base = (uint32_t)__cvta_generic_to_shared(Qs);
    uint32_t ks_base = (uint32_t)__cvta_generic_to_shared(Ks);
    const int lrow = tid >> 2;
    const int lc0  = (tid & 3) * 4;

    #define ISSUE_KT(T) do { \
        uint32_t _kb = ks_base + (uint32_t)(((T) % 3) * 4096) * 4u; \
        _Pragma("unroll") \
        for (int it = 0; it < 4; it++) { \
            int c = lc0 + it*16; \
            cp16(_kb + (uint32_t)(lrow*64 + (c ^ ((lrow & 7) << 2)))*4u, \
                 &k[((size_t)(b*Tz + (T)*64 + lrow))*Cz + h*HDz + c]); \
        } \
    } while(0)

    #pragma unroll
    for (int it = 0; it < 4; it++) {
        int c = lc0 + it*16;
        cp16(qs_base + (uint32_t)(lrow*64 + (c ^ ((lrow & 7) << 2)))*4u,
             &q[((size_t)(b*Tz + q0 + lrow))*Cz + h*HDz + c]);
    }
    ISSUE_KT(0);
    cp_commit();
    if (ntiles > 1) ISSUE_KT(1);
    cp_commit();

    for (int t = 0; t < ntiles; t++) {
        cp_wait<1>();
        __syncthreads();
        if (t + 2 < ntiles) ISSUE_KT(t + 2);
        cp_commit();
        const uint32_t* ks = Ks + (t % 3) * 4096;
        float acc[2][2][4];
        #pragma unroll
        for (int i = 0; i < 2; i++)
            #pragma unroll
            for (int j = 0; j < 2; j++)
                #pragma unroll
                for (int qq = 0; qq < 4; qq++) acc[i][j][qq] = 0.f;
        #pragma unroll
        for (int ks8 = 0; ks8 < 8; ks8++) {
            const int k8 = ks8 * 8;
            uint32_t af[2][4];
            #pragma unroll
            for (int mt = 0; mt < 2; mt++) {
                const int mr = wm*32 + mt*16 + gr;
                const int sw = (mr & 7) << 2;
                af[mt][0] = f2tf(__uint_as_float(Qs[ mr     *64 + ((k8 + gc    ) ^ sw)]));
                af[mt][1] = f2tf(__uint_as_float(Qs[(mr + 8)*64 + ((k8 + gc    ) ^ sw)]));
                af[mt][2] = f2tf(__uint_as_float(Qs[ mr     *64 + ((k8 + gc + 4) ^ sw)]));
                af[mt][3] = f2tf(__uint_as_float(Qs[(mr + 8)*64 + ((k8 + gc + 4) ^ sw)]));
            }
            uint32_t bf[2][2];
            #pragma unroll
            for (int nt = 0; nt < 2; nt++) {
                const int nr = wn*16 + nt*8 + gr;
                const int sw = (nr & 7) << 2;
                bf[nt][0] = f2tf(__uint_as_float(ks[nr*64 + ((k8 + gc    ) ^ sw)]));
                bf[nt][1] = f2tf(__uint_as_float(ks[nr*64 + ((k8 + gc + 4) ^ sw)]));
            }
            #pragma unroll
            for (int mt = 0; mt < 2; mt++)
                #pragma unroll
                for (int nt = 0; nt < 2; nt++)
                    mma_tf32(acc[mt][nt], af[mt], bf[nt]);
        }
        const int kt0 = t * 64;
        #pragma unroll
        for (int mt = 0; mt < 2; mt++) {
            #pragma unroll
            for (int nt = 0; nt < 2; nt++) {
                const int r = wm*32 + mt*16 + gr;
                const int c = kt0 + wn*16 + nt*8 + gc*2;
                *(float2*)&S[ r     *SST + c] = make_float2(acc[mt][nt][0]*0.125f, acc[mt][nt][1]*0.125f);
                *(float2*)&S[(r + 8)*SST + c] = make_float2(acc[mt][nt][2]*0.125f, acc[mt][nt][3]*0.125f);
            }
        }
    }
    __syncthreads();

    const int kmax = q0 + 64;
    for (int r = w; r < 64; r += 8) {
        const int qt = q0 + r;
        float* Sr = &S[r*SST];
        float mx = -3.0e38f;
        for (int kt = lane; kt < kmax; kt += 32) {
            float s = Sr[kt];
            if (kt <= qt) mx = fmaxf(mx, s);
        }
        mx = warp_max(mx);
        float sum = 0.f;
        for (int kt = lane; kt < kmax; kt += 32) {
            float e = (kt <= qt) ? __expf(Sr[kt] - mx) : 0.f;
            Sr[kt] = e;
            sum += e;
        }
        sum = warp_sum(sum);
        const float inv = 1.0f / sum;
        float* orow = att + ((size_t)bh*Tz + qt)*Tz;
        for (int kt = lane; kt < kmax; kt += 32) {
            float p = Sr[kt] * inv;
            Sr[kt] = p;
            orow[kt] = p;
        }
        for (int kt = kmax + lane; kt < Tz; kt += 32) orow[kt] = 0.f;
    }
    __syncthreads();

    uint32_t* Vs = Ks;
    const int kti = tid & 63;
    const int dg  = (tid >> 6) * 4;
    float4 vreg[4];
    #pragma unroll
    for (int it = 0; it < 4; it++)
        vreg[it] = *(const float4*)&v[((size_t)(b*Tz + kti))*Cz + h*HDz + dg + it*16];

    float acc2[2][2][4];
    #pragma unroll
    for (int i = 0; i < 2; i++)
        #pragma unroll
        for (int j = 0; j < 2; j++)
            #pragma unroll
            for (int qq = 0; qq < 4; qq++) acc2[i][j][qq] = 0.f;

    for (int t = 0; t < ntiles; t++) {
        __syncthreads();
        #pragma unroll
        for (int it = 0; it < 4; it++) {
            const int d0 = dg + it*16;
            const float4 vv = vreg[it];
            Vs[(d0+0)*64 + (kti ^ (((d0+0) & 7) << 2))] = f2tf(vv.x);
            Vs[(d0+1)*64 + (kti ^ (((d0+1) & 7) << 2))] = f2tf(vv.y);
            Vs[(d0+2)*64 + (kti ^ (((d0+2) & 7) << 2))] = f2tf(vv.z);
            Vs[(d0+3)*64 + (kti ^ (((d0+3) & 7) << 2))] = f2tf(vv.w);
        }
        if (t + 1 < ntiles) {
            #pragma unroll
            for (int it = 0; it < 4; it++)
                vreg[it] = *(const float4*)&v[((size_t)(b*Tz + (t+1)*64 + kti))*Cz + h*HDz + dg + it*16];
        }
        __syncthreads();
        const int kt0 = t * 64;
        #pragma unroll
        for (int ks8 = 0; ks8 < 8; ks8++) {
            const int k8 = ks8 * 8;
            uint32_t af[2][4];
            #pragma unroll
            for (int mt = 0; mt < 2; mt++) {
                const int mr = wm*32 + mt*16 + gr;
                af[mt][0] = f2tf(S[ mr     *SST + kt0 + k8 + gc    ]);
                af[mt][1] = f2tf(S[(mr + 8)*SST + kt0 + k8 + gc    ]);
                af[mt][2] = f2tf(S[ mr     *SST + kt0 + k8 + gc + 4]);
                af[mt][3] = f2tf(S[(mr + 8)*SST + kt0 + k8 + gc + 4]);
            }
            uint32_t bf[2][2];
            #pragma unroll
            for (int nt = 0; nt < 2; nt++) {
                const int nr = wn*16 + nt*8 + gr;
                const int sw = (nr & 7) << 2;
                bf[nt][0] = Vs[nr*64 + ((k8 + gc    ) ^ sw)];
                bf[nt][1] = Vs[nr*64 + ((k8 + gc + 4) ^ sw)];
            }
            #pragma unroll
            for (int mt = 0; mt < 2; mt++)
                #pragma unroll
                for (int nt = 0; nt < 2; nt++)
                    mma_tf32(acc2[mt][nt], af[mt], bf[nt]);
        }
    }

    float* Cp = y + ((size_t)(b*Tz + q0))*Cz + h*HDz;
    #pragma unroll
    for (int mt = 0; mt < 2; mt++) {
        #pragma unroll
        for (int nt = 0; nt < 2; nt++) {
            const int r = wm*32 + mt*16 + gr;
            const int c = wn*16 + nt*8 + gc*2;
            *(float2*)&Cp[(size_t) r     *Cz + c] = make_float2(roundtf(acc2[mt][nt][0]), roundtf(acc2[mt][nt][1]));
            *(float2*)&Cp[(size_t)(r + 8)*Cz + c] = make_float2(roundtf(acc2[mt][nt][2]), roundtf(acc2[mt][nt][3]));
        }
    }
    #undef ISSUE_KT
}

// ---------------- host launch ----------------
extern "C" void kernel_launch(void* const* d_in, const int* in_sizes, int n_in,
                              void* d_out, int out_size){
    const int*   idx    = (const int*)  d_in[0];
    const float* tok    = (const float*)d_in[1];
    const float* typ    = (const float*)d_in[2];
    const float* pos    = (const float*)d_in[3];
    const float* Wq     = (const float*)d_in[4];
    const float* bq     = (const float*)d_in[5];
    const float* Wk     = (const float*)d_in[6];
    const float* bk     = (const float*)d_in[7];
    const float* Wv     = (const float*)d_in[8];
    const float* bv     = (const float*)d_in[9];
    const float* Wp     = (const float*)d_in[10];
    const float* bp     = (const float*)d_in[11];
    const float* ln1_w  = (const float*)d_in[12];
    const float* ln1_b  = (const float*)d_in[13];
    const float* ln2_w  = (const float*)d_in[14];
    const float* ln2_b  = (const float*)d_in[15];
    const float* W1     = (const float*)d_in[16];
    const float* b1     = (const float*)d_in[17];
    const float* W2     = (const float*)d_in[18];
    const float* b2     = (const float*)d_in[19];
    const float* lnf_w  = (const float*)d_in[20];
    const float* lnf_b  = (const float*)d_in[21];
    const float* head_w = (const float*)d_in[22];

    float* out        = (float*)d_out;
    float* out_logits = out;
    float* out_x      = out + (size_t)Mz*Vz;
    float* out_att    = out_x + (size_t)Mz*Cz;

    float *px, *ph, *pq, *pk, *pv, *py, *pff;
    float *pwq, *pwk, *pwv, *pwp, *pw1, *pw2;
    cudaGetSymbolAddress((void**)&px,  g_x);
    cudaGetSymbolAddress((void**)&ph,  g_h);
    cudaGetSymbolAddress((void**)&pq,  g_q);
    cudaGetSymbolAddress((void**)&pk,  g_k);
    cudaGetSymbolAddress((void**)&pv,  g_v);
    cudaGetSymbolAddress((void**)&py,  g_y);
    cudaGetSymbolAddress((void**)&pff, g_ff);
    cudaGetSymbolAddress((void**)&pwq, g_wq);
    cudaGetSymbolAddress((void**)&pwk, g_wk);
    cudaGetSymbolAddress((void**)&pwv, g_wv);
    cudaGetSymbolAddress((void**)&pwp, g_wp);
    cudaGetSymbolAddress((void**)&pw1, g_w1);
    cudaGetSymbolAddress((void**)&pw2, g_w2);

    static bool attrs_set = false;
    if (!attrs_set) {
        cudaFuncSetAttribute((const void*)gemm_tf32_k<false,false>, cudaFuncAttributeMaxDynamicSharedMemorySize, GEMM_SMEM);
        cudaFuncSetAttribute((const void*)gemm_tf32_k<true,true>,   cudaFuncAttributeMaxDynamicSharedMemorySize, GEMM_SMEM);
        cudaFuncSetAttribute((const void*)qkv_k,                    cudaFuncAttributeMaxDynamicSharedMemorySize, GEMM_SMEM);
        cudaFuncSetAttribute((const void*)attn_fused_k,             cudaFuncAttributeMaxDynamicSharedMemorySize, ATTF_SMEM);
        attrs_set = true;
    }

    // per-call weight transpose + tf32 pre-round (deterministic, graph-capturable)
    dim3 tb(32, 8);
    wtrans_k<<<dim3(Cz/32,  Cz/32,  Lz), tb>>>(Wq, pwq, Cz, Cz);
    wtrans_k<<<dim3(Cz/32,  Cz/32,  Lz), tb>>>(Wk, pwk, Cz, Cz);
    wtrans_k<<<dim3(Cz/32,  Cz/32,  Lz), tb>>>(Wv, pwv, Cz, Cz);
    wtrans_k<<<dim3(Cz/32,  Cz/32,  Lz), tb>>>(Wp, pwp, Cz, Cz);
    wtrans_k<<<dim3(FFz/32, Cz/32,  Lz), tb>>>(W1, pw1, Cz, FFz);
    wtrans_k<<<dim3(Cz/32,  FFz/32, Lz), tb>>>(W2, pw2, FFz, Cz);

    embed_k<<<(Mz*Cz + 255)/256, 256>>>(idx, tok, typ, pos, px);

    dim3 gQKV3(Cz/BNt, Mz/BMt, 3);
    dim3 gP(Cz/BNt,  Mz/BMt);
    dim3 gFF1(FFz/BNt, Mz/BMt);
    dim3 gHead(Vz/64, Mz/64);
    dim3 gAtt(Tz/64, Bz*Hz);

    for (int l = 0; l < Lz; l++) {
        float* attL = out_att + (size_t)l*Bz*Hz*Tz*Tz;

        ln_k<true><<<Mz/8, 256>>>(px, ln1_w + (size_t)l*Cz, ln1_b + (size_t)l*Cz, ph);
        qkv_k<<<gQKV3, 256, GEMM_SMEM>>>(ph,
            pwq + (size_t)l*Cz*Cz, pwk + (size_t)l*Cz*Cz, pwv + (size_t)l*Cz*Cz,
            bq + (size_t)l*Cz, bk + (size_t)l*Cz, bv + (size_t)l*Cz,
            pq, pk, pv);
        attn_fused_k<<<gAtt, 256, ATTF_SMEM>>>(pq, pk, pv, attL, py);
        gemm_tf32_k<false,false><<<gP, 256, GEMM_SMEM>>>(py, pwp + (size_t)l*Cz*Cz,
            bp + (size_t)l*Cz, px, px, Cz, Cz);
        ln_k<true><<<Mz/8, 256>>>(px, ln2_w + (size_t)l*Cz, ln2_b + (size_t)l*Cz, ph);
        gemm_tf32_k<true,true><<<gFF1, 256, GEMM_SMEM>>>(ph, pw1 + (size_t)l*Cz*FFz,
            b1 + (size_t)l*FFz, nullptr, pff, FFz, Cz);
        gemm_tf32_k<false,false><<<gP, 256, GEMM_SMEM>>>(pff, pw2 + (size_t)l*FFz*Cz,
            b2 + (size_t)l*Cz, px, px, Cz, FFz);
    }

    ln_k<false><<<Mz/8, 256>>>(px, lnf_w, lnf_b, out_x);
    gemm_head_k<<<gHead, 256>>>(out_x, head_w, out_logits, Vz, Cz);
}

// round 6
// speedup vs baseline: 4.1503x; 1.0206x over previous
#include <cuda_runtime.h>
#include <cuda_bf16.h>
#include <math.h>
#include <stdint.h>

#define Bz 4
#define Tz 512
#define Cz 768
#define Hz 12
#define Lz 8
#define Vz 512
#define FFz (4*Cz)
#define HDz (Cz/Hz)
#define Mz (Bz*Tz)
#define EPSz 1e-5f

// ---------------- scratch ----------------
__device__ float g_x [Mz*Cz];
__device__ float g_h [Mz*Cz];
__device__ float g_q [Mz*Cz];
__device__ float g_k [Mz*Cz];
__device__ float g_v [Mz*Cz];
__device__ float g_y [Mz*Cz];
__device__ float g_ff[Mz*FFz];
// transposed + tf32-prerounded weights: [N][K] layout
__device__ float g_wq[Lz*Cz*Cz];
__device__ float g_wk[Lz*Cz*Cz];
__device__ float g_wv[Lz*Cz*Cz];
__device__ float g_wp[Lz*Cz*Cz];
__device__ float g_w1[Lz*Cz*FFz];
__device__ float g_w2[Lz*FFz*Cz];

// ---------------- warp reductions ----------------
__device__ __forceinline__ float warp_sum(float v){
    #pragma unroll
    for (int o = 16; o; o >>= 1) v += __shfl_xor_sync(0xffffffffu, v, o);
    return v;
}
__device__ __forceinline__ float warp_max(float v){
    #pragma unroll
    for (int o = 16; o; o >>= 1) v = fmaxf(v, __shfl_xor_sync(0xffffffffu, v, o));
    return v;
}

// ================= TF32 / mma / cp.async helpers =================
__device__ __forceinline__ uint32_t f2tf(float f){
    uint32_t u; asm("cvt.rna.tf32.f32 %0, %1;" : "=r"(u) : "f"(f)); return u;
}
__device__ __forceinline__ float roundtf(float f){ return __uint_as_float(f2tf(f)); }
__device__ __forceinline__ void mma_tf32(float* d, const uint32_t* a, const uint32_t* b){
    asm volatile(
        "mma.sync.aligned.m16n8k8.row.col.f32.tf32.tf32.f32 "
        "{%0,%1,%2,%3}, {%4,%5,%6,%7}, {%8,%9}, {%0,%1,%2,%3};\n"
        : "+f"(d[0]), "+f"(d[1]), "+f"(d[2]), "+f"(d[3])
        : "r"(a[0]), "r"(a[1]), "r"(a[2]), "r"(a[3]), "r"(b[0]), "r"(b[1]));
}
__device__ __forceinline__ void ldsm4(uint32_t* r, uint32_t addr){
    asm volatile("ldmatrix.sync.aligned.m8n8.x4.shared.b16 {%0,%1,%2,%3}, [%4];"
        : "=r"(r[0]), "=r"(r[1]), "=r"(r[2]), "=r"(r[3]) : "r"(addr));
}
__device__ __forceinline__ void cp16(uint32_t dst, const float* src){
    asm volatile("cp.async.cg.shared.global [%0], [%1], 16;" :: "r"(dst), "l"(src));
}
__device__ __forceinline__ void cp_commit(){ asm volatile("cp.async.commit_group;"); }
template<int N> __device__ __forceinline__ void cp_wait(){ asm volatile("cp.async.wait_group %0;" :: "n"(N)); }

// ---------------- embeddings ----------------
__global__ void embed_k(const int* __restrict__ idx, const float* __restrict__ tok,
                        const float* __restrict__ typ, const float* __restrict__ pos,
                        float* __restrict__ x){
    int i = blockIdx.x * blockDim.x + threadIdx.x;
    if (i >= Mz*Cz) return;
    int c = i % Cz;
    int bt = i / Cz;
    int t = bt % Tz;
    x[i] = tok[(size_t)idx[bt]*Cz + c] + pos[(size_t)t*Cz + c] + typ[Cz + c];
}

// ---------------- weight transpose + tf32 pre-round: src[K,N] -> dst[N,K] ----------------
__global__ void wtrans_k(const float* __restrict__ src, float* __restrict__ dst,
                         int K, int N){
    __shared__ float tile[32][33];
    const size_t mat = (size_t)blockIdx.z * (size_t)K * N;
    src += mat; dst += mat;
    int n0 = blockIdx.x*32, k0 = blockIdx.y*32;
    #pragma unroll
    for (int i = threadIdx.y; i < 32; i += 8)
        tile[i][threadIdx.x] = src[(size_t)(k0+i)*N + n0 + threadIdx.x];
    __syncthreads();
    #pragma unroll
    for (int i = threadIdx.y; i < 32; i += 8)
        dst[(size_t)(n0+i)*K + k0 + threadIdx.x] = roundtf(tile[threadIdx.x][i]);
}

// ---------------- layernorm: warp per row ----------------
template<bool ROUND>
__global__ void ln_k(const float* __restrict__ in, const float* __restrict__ w,
                     const float* __restrict__ b, float* __restrict__ out){
    int row = blockIdx.x*8 + (threadIdx.x >> 5);
    int lane = threadIdx.x & 31;
    const float* xr = in + (size_t)row * Cz;
    float v[24];
    float s = 0.f, s2 = 0.f;
    #pragma unroll
    for (int i = 0; i < 24; i++) {
        float t = xr[lane + i*32];
        v[i] = t; s += t; s2 += t*t;
    }
    s  = warp_sum(s);
    s2 = warp_sum(s2);
    float mean = s * (1.0f/Cz);
    float inv  = rsqrtf(s2 * (1.0f/Cz) - mean*mean + EPSz);
    float* orow = out + (size_t)row * Cz;
    #pragma unroll
    for (int i = 0; i < 24; i++) {
        int c = lane + i*32;
        float o = (v[i] - mean) * inv * w[c] + b[c];
        orow[c] = ROUND ? roundtf(o) : o;
    }
}

// ================= TF32 tensor-core GEMM: ldmatrix both operands, 4-stage =================
#define BMt 128
#define BNt 64
#define BKt 32
#define AS_SZ (BMt*BKt)
#define BS_SZ (BNt*BKt)
#define STAGES 4
#define GEMM_SMEM (STAGES*(AS_SZ+BS_SZ)*4)

template<bool GELU, bool ROUND>
__device__ __forceinline__ void gemm_body(
    uint32_t* As, uint32_t* Bs,
    const float* __restrict__ A, const float* __restrict__ Bt,
    const float* __restrict__ bias, const float* __restrict__ res,
    float* __restrict__ Cm, int Ndim, int Kdim, int m0, int n0)
{
    const int tid  = threadIdx.x;
    const int lane = tid & 31;
    const int w    = tid >> 5;
    const int wm   = w >> 1;
    const int wn   = w & 1;
    const int gr   = lane >> 2;
    const int gc   = lane & 3;

    const int amr = tid >> 3;
    const int ak  = (tid & 7) << 2;

    uint32_t as_base = (uint32_t)__cvta_generic_to_shared(As);
    uint32_t bs_base = (uint32_t)__cvta_generic_to_shared(Bs);

    uint32_t adst[4], bdst[2];
    #pragma unroll
    for (int i = 0; i < 4; i++) {
        int m = amr + i*32;
        adst[i] = (uint32_t)(m*BKt + (ak ^ ((m & 7) << 2))) * 4u;
    }
    #pragma unroll
    for (int j = 0; j < 2; j++) {
        int n = amr + j*32;
        bdst[j] = (uint32_t)(n*BKt + (ak ^ ((n & 7) << 2))) * 4u;
    }

    const int nk = Kdim / BKt;

    #define ISSUE(T) do { \
        int _buf = (T) % STAGES; int _k0 = (T) * BKt; \
        uint32_t _ab = as_base + (uint32_t)(_buf*AS_SZ*4); \
        uint32_t _bb = bs_base + (uint32_t)(_buf*BS_SZ*4); \
        _Pragma("unroll") \
        for (int i = 0; i < 4; i++) \
            cp16(_ab + adst[i], &A[(size_t)(m0 + amr + i*32)*Kdim + _k0 + ak]); \
        _Pragma("unroll") \
        for (int j = 0; j < 2; j++) \
            cp16(_bb + bdst[j], &Bt[(size_t)(n0 + amr + j*32)*Kdim + _k0 + ak]); \
    } while(0)

    const int a_s4 = (lane >> 4) << 2;
    const int b_s4 = (lane >> 3) << 2;
    int a_m[2], b_n[4];
    #pragma unroll
    for (int mt = 0; mt < 2; mt++) a_m[mt] = wm*32 + mt*16 + (lane & 15);
    #pragma unroll
    for (int nt = 0; nt < 4; nt++) b_n[nt] = wn*32 + nt*8 + (lane & 7);

    float acc[2][4][4];
    #pragma unroll
    for (int i = 0; i < 2; i++)
        #pragma unroll
        for (int j = 0; j < 4; j++)
            #pragma unroll
            for (int q = 0; q < 4; q++) acc[i][j][q] = 0.f;

    ISSUE(0); cp_commit();
    ISSUE(1); cp_commit();
    ISSUE(2); cp_commit();

    for (int t = 0; t < nk; t++) {
        cp_wait<2>();
        __syncthreads();
        if (t + 3 < nk) ISSUE(t + 3);
        cp_commit();
        const uint32_t ab = as_base + (uint32_t)((t % STAGES)*AS_SZ*4);
        const uint32_t bb = bs_base + (uint32_t)((t % STAGES)*BS_SZ*4);

        uint32_t breg[4][8];
        #pragma unroll
        for (int nt = 0; nt < 4; nt++) {
            const int nr = b_n[nt];
            const int sw = (nr & 7) << 2;
            ldsm4(&breg[nt][0], bb + (uint32_t)(nr*BKt + ((0  + b_s4) ^ sw))*4u);
            ldsm4(&breg[nt][4], bb + (uint32_t)(nr*BKt + ((16 + b_s4) ^ sw))*4u);
        }
        #pragma unroll
        for (int ks = 0; ks < 4; ks++) {
            const int k8 = ks * 8;
            uint32_t areg[2][4];
            #pragma unroll
            for (int mt = 0; mt < 2; mt++) {
                const int mr = a_m[mt];
                const int sw = (mr & 7) << 2;
                ldsm4(areg[mt], ab + (uint32_t)(mr*BKt + ((k8 + a_s4) ^ sw))*4u);
            }
            #pragma unroll
            for (int mt = 0; mt < 2; mt++)
                #pragma unroll
                for (int nt = 0; nt < 4; nt++)
                    mma_tf32(acc[mt][nt], areg[mt], &breg[nt][ks*2]);
        }
    }
    #undef ISSUE

    #pragma unroll
    for (int mt = 0; mt < 2; mt++) {
        #pragma unroll
        for (int nt = 0; nt < 4; nt++) {
            const int r0 = m0 + wm*32 + mt*16 + gr;
            const int c0 = n0 + wn*32 + nt*8 + gc*2;
            #pragma unroll
            for (int half = 0; half < 2; half++) {
                const int r = r0 + half*8;
                float v0 = acc[mt][nt][half*2 + 0];
                float v1 = acc[mt][nt][half*2 + 1];
                if (bias) { v0 += bias[c0]; v1 += bias[c0+1]; }
                if (GELU) {
                    v0 = 0.5f * v0 * (1.0f + erff(v0 * 0.70710678118654752f));
                    v1 = 0.5f * v1 * (1.0f + erff(v1 * 0.70710678118654752f));
                }
                if (res) {
                    v0 += res[(size_t)r*Ndim + c0];
                    v1 += res[(size_t)r*Ndim + c0 + 1];
                }
                if (ROUND) { v0 = roundtf(v0); v1 = roundtf(v1); }
                *(float2*)&Cm[(size_t)r*Ndim + c0] = make_float2(v0, v1);
            }
        }
    }
}

extern __shared__ unsigned char smem_raw[];

template<bool GELU, bool ROUND>
__global__ void __launch_bounds__(256, 2)
gemm_tf32_k(const float* __restrict__ A, const float* __restrict__ Bt,
            const float* __restrict__ bias, const float* __restrict__ res,
            float* __restrict__ Cm, int Ndim, int Kdim){
    uint32_t* As = (uint32_t*)smem_raw;
    uint32_t* Bs = As + STAGES*AS_SZ;
    gemm_body<GELU, ROUND>(As, Bs, A, Bt, bias, res, Cm, Ndim, Kdim,
                           blockIdx.y*BMt, blockIdx.x*BNt);
}

__global__ void __launch_bounds__(256, 2)
qkv_k(const float* __restrict__ h,
      const float* __restrict__ Wq, const float* __restrict__ Wk, const float* __restrict__ Wv,
      const float* __restrict__ bq, const float* __restrict__ bk, const float* __restrict__ bv,
      float* __restrict__ q, float* __restrict__ k, float* __restrict__ v){
    uint32_t* As = (uint32_t*)smem_raw;
    uint32_t* Bs = As + STAGES*AS_SZ;
    const float* W  = (blockIdx.z == 0) ? Wq : (blockIdx.z == 1) ? Wk : Wv;
    const float* bb = (blockIdx.z == 0) ? bq : (blockIdx.z == 1) ? bk : bv;
    float*       o  = (blockIdx.z == 0) ? q  : (blockIdx.z == 1) ? k  : v;
    gemm_body<false, true>(As, Bs, h, W, bb, nullptr, o, Cz, Cz,
                           blockIdx.y*BMt, blockIdx.x*BNt);
}

// ---------------- fp32 SIMT GEMM (head only, B transposed) ----------------
__global__ void gemm_head_k(const float* __restrict__ A, const float* __restrict__ Bm,
                            float* __restrict__ Cm, int Ndim, int Kdim){
    __shared__ float As[64][17];
    __shared__ float Bs[16][64];
    int n0 = blockIdx.x * 64, m0 = blockIdx.y * 64;
    int tid = threadIdx.x;
    int tx = tid & 15, ty = tid >> 4;
    float acc[4][4] = {};
    for (int k0 = 0; k0 < Kdim; k0 += 16) {
        {
            int m = tid >> 2, kq = (tid & 3) * 4;
            float4 a4 = *(const float4*)&A[(size_t)(m0+m)*Kdim + k0 + kq];
            As[m][kq+0] = a4.x; As[m][kq+1] = a4.y; As[m][kq+2] = a4.z; As[m][kq+3] = a4.w;
        }
        {
            int n = tid >> 2, kq = (tid & 3) * 4;
            float4 b4 = *(const float4*)&Bm[(size_t)(n0+n)*Kdim + k0 + kq];
            Bs[kq+0][n] = b4.x; Bs[kq+1][n] = b4.y; Bs[kq+2][n] = b4.z; Bs[kq+3][n] = b4.w;
        }
        __syncthreads();
        #pragma unroll
        for (int kk = 0; kk < 16; kk++) {
            float a[4];
            #pragma unroll
            for (int i = 0; i < 4; i++) a[i] = As[ty*4+i][kk];
            float4 b4 = *(float4*)&Bs[kk][tx*4];
            float bb[4] = {b4.x, b4.y, b4.z, b4.w};
            #pragma unroll
            for (int i = 0; i < 4; i++)
                #pragma unroll
                for (int j = 0; j < 4; j++)
                    acc[i][j] = fmaf(a[i], bb[j], acc[i][j]);
        }
        __syncthreads();
    }
    #pragma unroll
    for (int i = 0; i < 4; i++) {
        int m = m0 + ty*4 + i;
        #pragma unroll
        for (int j = 0; j < 4; j++)
            Cm[(size_t)m*Ndim + n0 + tx*4 + j] = acc[i][j];
    }
}

// ============ fused attention v2: 512 threads, ldmatrix, zero in-loop cvt ============
// Q/K/V are tf32-pre-rounded fp32 -> raw bits are valid mma operands.
#define SST 516
#define ATTF_SMEM ((64*SST + 64*64 + 3*64*64)*4)

__global__ void __launch_bounds__(512, 1)
attn_fused_k(const float* __restrict__ q, const float* __restrict__ k,
             const float* __restrict__ v, float* __restrict__ att,
             float* __restrict__ y){
    float*    S  = (float*)smem_raw;            // [64][SST]
    uint32_t* Qs = (uint32_t*)(S + 64*SST);     // [64][64] swizzled
    uint32_t* Ks = Qs + 64*64;                  // 3 x [64][64] swizzled

    const int qb = gridDim.x - 1 - blockIdx.x;  // heavy blocks first
    const int q0 = qb * 64;
    const int bh = blockIdx.y;
    const int b = bh / Hz, h = bh % Hz;
    const int tid  = threadIdx.x;
    const int lane = tid & 31;
    const int w    = tid >> 5;     // 0..15
    const int wm   = w >> 2;       // 0..3
    const int wn   = w & 3;        // 0..3
    const int gr   = lane >> 2;
    const int gc   = lane & 3;
    const int ntiles = qb + 1;

    uint32_t s_base  = (uint32_t)__cvta_generic_to_shared(S);
    uint32_t qs_base = (uint32_t)__cvta_generic_to_shared(Qs);
    uint32_t ks_base = (uint32_t)__cvta_generic_to_shared(Ks);

    // cp.async staging: 64 rows x 64 floats, 512 threads -> 2 chunks each
    const int lrow = tid >> 3;          // 0..63
    const int lc   = (tid & 7) * 4;     // 0..28
    const int lsw  = (lrow & 7) << 2;
    const uint32_t st0 = (uint32_t)(lrow*64 + ( lc        ^ lsw)) * 4u;
    const uint32_t st1 = (uint32_t)(lrow*64 + ((lc + 32)  ^ lsw)) * 4u;

    #define ISSUE_KT(T) do { \
        uint32_t _kb = ks_base + (uint32_t)(((T) % 3) * 4096) * 4u; \
        const float* _kp = &k[((size_t)(b*Tz + (T)*64 + lrow))*Cz + h*HDz]; \
        cp16(_kb + st0, _kp + lc); \
        cp16(_kb + st1, _kp + lc + 32); \
    } while(0)

    {
        const float* qp = &q[((size_t)(b*Tz + q0 + lrow))*Cz + h*HDz];
        cp16(qs_base + st0, qp + lc);
        cp16(qs_base + st1, qp + lc + 32);
    }
    ISSUE_KT(0);
    cp_commit();
    if (ntiles > 1) ISSUE_KT(1);
    cp_commit();

    // fragment lane roles
    const int a_s4 = (lane >> 4) << 2;              // 0 or 4
    const int b_s4 = (lane >> 3) << 2;              // 0,4,8,12
    const int am   = wm*16 + (lane & 15);           // A rows
    const int asw  = (am & 7) << 2;
    int b_n[2]; int bsw[2];
    #pragma unroll
    for (int nt = 0; nt < 2; nt++) {
        b_n[nt] = wn*16 + nt*8 + (lane & 7);
        bsw[nt] = (b_n[nt] & 7) << 2;
    }

    // -------- phase 1: S = QK^T * scale --------
    for (int t = 0; t < ntiles; t++) {
        cp_wait<1>();
        __syncthreads();
        if (t + 2 < ntiles) ISSUE_KT(t + 2);
        cp_commit();
        const uint32_t kb = ks_base + (uint32_t)((t % 3) * 4096) * 4u;

        uint32_t breg[2][16];
        #pragma unroll
        for (int nt = 0; nt < 2; nt++)
            #pragma unroll
            for (int qk = 0; qk < 4; qk++)
                ldsm4(&breg[nt][qk*4], kb + (uint32_t)(b_n[nt]*64 + ((qk*16 + b_s4) ^ bsw[nt]))*4u);

        float acc[2][4] = {};
        #pragma unroll
        for (int ks8 = 0; ks8 < 8; ks8++) {
            uint32_t areg[4];
            ldsm4(areg, qs_base + (uint32_t)(am*64 + ((ks8*8 + a_s4) ^ asw))*4u);
            mma_tf32(acc[0], areg, &breg[0][ks8*2]);
            mma_tf32(acc[1], areg, &breg[1][ks8*2]);
        }
        const int kt0 = t * 64;
        #pragma unroll
        for (int nt = 0; nt < 2; nt++) {
            const int r = wm*16 + gr;
            const int c = kt0 + wn*16 + nt*8 + gc*2;
            *(float2*)&S[ r     *SST + c] = make_float2(acc[nt][0]*0.125f, acc[nt][1]*0.125f);
            *(float2*)&S[(r + 8)*SST + c] = make_float2(acc[nt][2]*0.125f, acc[nt][3]*0.125f);
        }
    }
    __syncthreads();

    // -------- softmax (warp per row): att <- p (fp32), S <- tf32 bits of p --------
    const int kmax = q0 + 64;
    for (int r = w; r < 64; r += 16) {
        const int qt = q0 + r;
        float* Sr = &S[r*SST];
        float mx = -3.0e38f;
        for (int kt = lane; kt < kmax; kt += 32) {
            float s = Sr[kt];
            if (kt <= qt) mx = fmaxf(mx, s);
        }
        mx = warp_max(mx);
        float sum = 0.f;
        for (int kt = lane; kt < kmax; kt += 32) {
            float e = (kt <= qt) ? __expf(Sr[kt] - mx) : 0.f;
            Sr[kt] = e;
            sum += e;
        }
        sum = warp_sum(sum);
        const float inv = 1.0f / sum;
        float* orow = att + ((size_t)bh*Tz + qt)*Tz;
        for (int kt = lane; kt < kmax; kt += 32) {
            float p = Sr[kt] * inv;
            orow[kt] = p;
            Sr[kt] = roundtf(p);      // tf32 bits for phase-2 ldmatrix
        }
        for (int kt = kmax + lane; kt < Tz; kt += 32) orow[kt] = 0.f;
    }
    __syncthreads();

    // -------- phase 2: y = P @ V --------
    uint32_t* Vs = Ks;               // reuse buffer 0: [d][kt] swizzled
    const int kti = tid & 63;
    const int dg8 = (tid >> 6) * 8;  // 0..56
    float4 vreg[2];
    #pragma unroll
    for (int it = 0; it < 2; it++)
        vreg[it] = *(const float4*)&v[((size_t)(b*Tz + kti))*Cz + h*HDz + dg8 + it*4];

    float acc2[2][4] = {};

    for (int t = 0; t < ntiles; t++) {
        __syncthreads();     // prior reads of Vs done
        #pragma unroll
        for (int it = 0; it < 2; it++) {
            const float vv[4] = {vreg[it].x, vreg[it].y, vreg[it].z, vreg[it].w};
            #pragma unroll
            for (int j = 0; j < 4; j++) {
                const int d = dg8 + it*4 + j;
                Vs[d*64 + (kti ^ ((d & 7) << 2))] = __float_as_uint(vv[j]);
            }
        }
        if (t + 1 < ntiles) {
            #pragma unroll
            for (int it = 0; it < 2; it++)
                vreg[it] = *(const float4*)&v[((size_t)(b*Tz + (t+1)*64 + kti))*Cz + h*HDz + dg8 + it*4];
        }
        __syncthreads();
        const int kt0 = t * 64;

        uint32_t breg[2][16];
        #pragma unroll
        for (int nt = 0; nt < 2; nt++)
            #pragma unroll
            for (int qk = 0; qk < 4; qk++)
                ldsm4(&breg[nt][qk*4], ks_base + (uint32_t)(b_n[nt]*64 + ((qk*16 + b_s4) ^ bsw[nt]))*4u);

        #pragma unroll
        for (int ks8 = 0; ks8 < 8; ks8++) {
            uint32_t areg[4];
            ldsm4(areg, s_base + (uint32_t)(am*SST + kt0 + ks8*8 + a_s4)*4u);
            mma_tf32(acc2[0], areg, &breg[0][ks8*2]);
            mma_tf32(acc2[1], areg, &breg[1][ks8*2]);
        }
    }

    // write y (fused transpose into [B,T,C]), pre-rounded for next GEMM
    float* Cp = y + ((size_t)(b*Tz + q0))*Cz + h*HDz;
    #pragma unroll
    for (int nt = 0; nt < 2; nt++) {
        const int r = wm*16 + gr;
        const int c = wn*16 + nt*8 + gc*2;
        *(float2*)&Cp[(size_t) r     *Cz + c] = make_float2(roundtf(acc2[nt][0]), roundtf(acc2[nt][1]));
        *(float2*)&Cp[(size_t)(r + 8)*Cz + c] = make_float2(roundtf(acc2[nt][2]), roundtf(acc2[nt][3]));
    }
    #undef ISSUE_KT
}

// ---------------- host launch ----------------
extern "C" void kernel_launch(void* const* d_in, const int* in_sizes, int n_in,
                              void* d_out, int out_size){
    const int*   idx    = (const int*)  d_in[0];
    const float* tok    = (const float*)d_in[1];
    const float* typ    = (const float*)d_in[2];
    const float* pos    = (const float*)d_in[3];
    const float* Wq     = (const float*)d_in[4];
    const float* bq     = (const float*)d_in[5];
    const float* Wk     = (const float*)d_in[6];
    const float* bk     = (const float*)d_in[7];
    const float* Wv     = (const float*)d_in[8];
    const float* bv     = (const float*)d_in[9];
    const float* Wp     = (const float*)d_in[10];
    const float* bp     = (const float*)d_in[11];
    const float* ln1_w  = (const float*)d_in[12];
    const float* ln1_b  = (const float*)d_in[13];
    const float* ln2_w  = (const float*)d_in[14];
    const float* ln2_b  = (const float*)d_in[15];
    const float* W1     = (const float*)d_in[16];
    const float* b1     = (const float*)d_in[17];
    const float* W2     = (const float*)d_in[18];
    const float* b2     = (const float*)d_in[19];
    const float* lnf_w  = (const float*)d_in[20];
    const float* lnf_b  = (const float*)d_in[21];
    const float* head_w = (const float*)d_in[22];

    float* out        = (float*)d_out;
    float* out_logits = out;
    float* out_x      = out + (size_t)Mz*Vz;
    float* out_att    = out_x + (size_t)Mz*Cz;

    float *px, *ph, *pq, *pk, *pv, *py, *pff;
    float *pwq, *pwk, *pwv, *pwp, *pw1, *pw2;
    cudaGetSymbolAddress((void**)&px,  g_x);
    cudaGetSymbolAddress((void**)&ph,  g_h);
    cudaGetSymbolAddress((void**)&pq,  g_q);
    cudaGetSymbolAddress((void**)&pk,  g_k);
    cudaGetSymbolAddress((void**)&pv,  g_v);
    cudaGetSymbolAddress((void**)&py,  g_y);
    cudaGetSymbolAddress((void**)&pff, g_ff);
    cudaGetSymbolAddress((void**)&pwq, g_wq);
    cudaGetSymbolAddress((void**)&pwk, g_wk);
    cudaGetSymbolAddress((void**)&pwv, g_wv);
    cudaGetSymbolAddress((void**)&pwp, g_wp);
    cudaGetSymbolAddress((void**)&pw1, g_w1);
    cudaGetSymbolAddress((void**)&pw2, g_w2);

    static bool attrs_set = false;
    if (!attrs_set) {
        cudaFuncSetAttribute((const void*)gemm_tf32_k<false,false>, cudaFuncAttributeMaxDynamicSharedMemorySize, GEMM_SMEM);
        cudaFuncSetAttribute((const void*)gemm_tf32_k<true,true>,   cudaFuncAttributeMaxDynamicSharedMemorySize, GEMM_SMEM);
        cudaFuncSetAttribute((const void*)qkv_k,                    cudaFuncAttributeMaxDynamicSharedMemorySize, GEMM_SMEM);
        cudaFuncSetAttribute((const void*)attn_fused_k,             cudaFuncAttributeMaxDynamicSharedMemorySize, ATTF_SMEM);
        attrs_set = true;
    }

    dim3 tb(32, 8);
    wtrans_k<<<dim3(Cz/32,  Cz/32,  Lz), tb>>>(Wq, pwq, Cz, Cz);
    wtrans_k<<<dim3(Cz/32,  Cz/32,  Lz), tb>>>(Wk, pwk, Cz, Cz);
    wtrans_k<<<dim3(Cz/32,  Cz/32,  Lz), tb>>>(Wv, pwv, Cz, Cz);
    wtrans_k<<<dim3(Cz/32,  Cz/32,  Lz), tb>>>(Wp, pwp, Cz, Cz);
    wtrans_k<<<dim3(FFz/32, Cz/32,  Lz), tb>>>(W1, pw1, Cz, FFz);
    wtrans_k<<<dim3(Cz/32,  FFz/32, Lz), tb>>>(W2, pw2, FFz, Cz);

    embed_k<<<(Mz*Cz + 255)/256, 256>>>(idx, tok, typ, pos, px);

    dim3 gQKV3(Cz/BNt, Mz/BMt, 3);
    dim3 gP(Cz/BNt,  Mz/BMt);
    dim3 gFF1(FFz/BNt, Mz/BMt);
    dim3 gHead(Vz/64, Mz/64);
    dim3 gAtt(Tz/64, Bz*Hz);

    for (int l = 0; l < Lz; l++) {
        float* attL = out_att + (size_t)l*Bz*Hz*Tz*Tz;

        ln_k<true><<<Mz/8, 256>>>(px, ln1_w + (size_t)l*Cz, ln1_b + (size_t)l*Cz, ph);
        qkv_k<<<gQKV3, 256, GEMM_SMEM>>>(ph,
            pwq + (size_t)l*Cz*Cz, pwk + (size_t)l*Cz*Cz, pwv + (size_t)l*Cz*Cz,
            bq + (size_t)l*Cz, bk + (size_t)l*Cz, bv + (size_t)l*Cz,
            pq, pk, pv);
        attn_fused_k<<<gAtt, 512, ATTF_SMEM>>>(pq, pk, pv, attL, py);
        gemm_tf32_k<false,false><<<gP, 256, GEMM_SMEM>>>(py, pwp + (size_t)l*Cz*Cz,
            bp + (size_t)l*Cz, px, px, Cz, Cz);
        ln_k<true><<<Mz/8, 256>>>(px, ln2_w + (size_t)l*Cz, ln2_b + (size_t)l*Cz, ph);
        gemm_tf32_k<true,true><<<gFF1, 256, GEMM_SMEM>>>(ph, pw1 + (size_t)l*Cz*FFz,
            b1 + (size_t)l*FFz, nullptr, pff, FFz, Cz);
        gemm_tf32_k<false,false><<<gP, 256, GEMM_SMEM>>>(pff, pw2 + (size_t)l*FFz*Cz,
            b2 + (size_t)l*Cz, px, px, Cz, FFz);
    }

    ln_k<false><<<Mz/8, 256>>>(px, lnf_w, lnf_b, out_x);
    gemm_head_k<<<gHead, 256>>>(out_x, head_w, out_logits, Vz, Cz);
}

// round 7
// speedup vs baseline: 5.6111x; 1.3520x over previous
#include <cuda_runtime.h>
#include <cuda_bf16.h>
#include <cuda_fp16.h>
#include <math.h>
#include <stdint.h>

#define Bz 4
#define Tz 512
#define Cz 768
#define Hz 12
#define Lz 8
#define Vz 512
#define FFz (4*Cz)
#define HDz (Cz/Hz)
#define Mz (Bz*Tz)
#define EPSz 1e-5f

// ---------------- scratch ----------------
__device__ float  g_x [Mz*Cz];
__device__ __half g_h [Mz*Cz];
__device__ __half g_q [Mz*Cz];
__device__ __half g_k [Mz*Cz];
__device__ __half g_v [Mz*Cz];
__device__ __half g_y [Mz*Cz];
__device__ __half g_ff[Mz*FFz];
// transposed fp16 weights: [N][K]
__device__ __half g_wq[Lz*Cz*Cz];
__device__ __half g_wk[Lz*Cz*Cz];
__device__ __half g_wv[Lz*Cz*Cz];
__device__ __half g_wp[Lz*Cz*Cz];
__device__ __half g_w1[Lz*Cz*FFz];
__device__ __half g_w2[Lz*FFz*Cz];

// ---------------- warp reductions ----------------
__device__ __forceinline__ float warp_sum(float v){
    #pragma unroll
    for (int o = 16; o; o >>= 1) v += __shfl_xor_sync(0xffffffffu, v, o);
    return v;
}
__device__ __forceinline__ float warp_max(float v){
    #pragma unroll
    for (int o = 16; o; o >>= 1) v = fmaxf(v, __shfl_xor_sync(0xffffffffu, v, o));
    return v;
}

// ================= mma / ldmatrix / cp.async helpers =================
__device__ __forceinline__ void mma_f16(float* d, const uint32_t* a, const uint32_t* b){
    asm volatile(
        "mma.sync.aligned.m16n8k16.row.col.f32.f16.f16.f32 "
        "{%0,%1,%2,%3}, {%4,%5,%6,%7}, {%8,%9}, {%0,%1,%2,%3};\n"
        : "+f"(d[0]), "+f"(d[1]), "+f"(d[2]), "+f"(d[3])
        : "r"(a[0]), "r"(a[1]), "r"(a[2]), "r"(a[3]), "r"(b[0]), "r"(b[1]));
}
__device__ __forceinline__ void ldsm4(uint32_t* r, uint32_t addr){
    asm volatile("ldmatrix.sync.aligned.m8n8.x4.shared.b16 {%0,%1,%2,%3}, [%4];"
        : "=r"(r[0]), "=r"(r[1]), "=r"(r[2]), "=r"(r[3]) : "r"(addr));
}
__device__ __forceinline__ void ldsm4t(uint32_t* r, uint32_t addr){
    asm volatile("ldmatrix.sync.aligned.m8n8.x4.trans.shared.b16 {%0,%1,%2,%3}, [%4];"
        : "=r"(r[0]), "=r"(r[1]), "=r"(r[2]), "=r"(r[3]) : "r"(addr));
}
__device__ __forceinline__ void cp16(uint32_t dst, const void* src){
    asm volatile("cp.async.cg.shared.global [%0], [%1], 16;" :: "r"(dst), "l"(src));
}
__device__ __forceinline__ void cp_commit(){ asm volatile("cp.async.commit_group;"); }
template<int N> __device__ __forceinline__ void cp_wait(){ asm volatile("cp.async.wait_group %0;" :: "n"(N)); }
__device__ __forceinline__ uint32_t h2u(__half2 h){ return *(uint32_t*)&h; }

// ---------------- embeddings ----------------
__global__ void embed_k(const int* __restrict__ idx, const float* __restrict__ tok,
                        const float* __restrict__ typ, const float* __restrict__ pos,
                        float* __restrict__ x){
    int i = blockIdx.x * blockDim.x + threadIdx.x;
    if (i >= Mz*Cz) return;
    int c = i % Cz;
    int bt = i / Cz;
    int t = bt % Tz;
    x[i] = tok[(size_t)idx[bt]*Cz + c] + pos[(size_t)t*Cz + c] + typ[Cz + c];
}

// ---------------- weight transpose + fp16 convert: src[K,N] fp32 -> dst[N,K] half ----------------
__global__ void wtrans_k(const float* __restrict__ src, __half* __restrict__ dst,
                         int K, int N){
    __shared__ float tile[32][33];
    src += (size_t)blockIdx.z * (size_t)K * N;
    dst += (size_t)blockIdx.z * (size_t)K * N;
    int n0 = blockIdx.x*32, k0 = blockIdx.y*32;
    #pragma unroll
    for (int i = threadIdx.y; i < 32; i += 8)
        tile[i][threadIdx.x] = src[(size_t)(k0+i)*N + n0 + threadIdx.x];
    __syncthreads();
    #pragma unroll
    for (int i = threadIdx.y; i < 32; i += 8)
        dst[(size_t)(n0+i)*K + k0 + threadIdx.x] = __float2half_rn(tile[threadIdx.x][i]);
}

// ---------------- layernorm: warp per row ----------------
template<bool OUTHALF>
__global__ void ln_k(const float* __restrict__ in, const float* __restrict__ w,
                     const float* __restrict__ b, void* __restrict__ outp){
    int row = blockIdx.x*8 + (threadIdx.x >> 5);
    int lane = threadIdx.x & 31;
    const float* xr = in + (size_t)row * Cz;
    float2 v[12];
    float s = 0.f, s2 = 0.f;
    #pragma unroll
    for (int i = 0; i < 12; i++) {
        float2 t = *(const float2*)&xr[2*lane + 64*i];
        v[i] = t; s += t.x + t.y; s2 += t.x*t.x + t.y*t.y;
    }
    s  = warp_sum(s);
    s2 = warp_sum(s2);
    float mean = s * (1.0f/Cz);
    float inv  = rsqrtf(s2 * (1.0f/Cz) - mean*mean + EPSz);
    #pragma unroll
    for (int i = 0; i < 12; i++) {
        int c = 2*lane + 64*i;
        float o0 = (v[i].x - mean) * inv * w[c]   + b[c];
        float o1 = (v[i].y - mean) * inv * w[c+1] + b[c+1];
        if (OUTHALF)
            *(__half2*)((__half*)outp + (size_t)row*Cz + c) = __floats2half2_rn(o0, o1);
        else
            *(float2*)((float*)outp + (size_t)row*Cz + c) = make_float2(o0, o1);
    }
}

// ================= FP16 tensor-core GEMM: m16n8k16, BK=64, 4-stage =================
#define BMh 128
#define BNh 64
#define BKh 64
#define ASZh (BMh*BKh)   // halfs
#define BSZh (BNh*BKh)
#define STG 4
#define GEMM_SMEM (STG*(ASZh+BSZh)*2)   // 96 KB

template<bool GELU, bool OUTHALF>
__device__ __forceinline__ void gemm_body(
    __half* As, __half* Bs,
    const __half* __restrict__ A, const __half* __restrict__ Bt,
    const float* __restrict__ bias, const float* __restrict__ res,
    void* __restrict__ Cm, int Ndim, int Kdim, int m0, int n0)
{
    const int tid  = threadIdx.x;
    const int lane = tid & 31;
    const int w    = tid >> 5;
    const int wm   = w >> 1;      // 0..3
    const int wn   = w & 1;       // 0..1
    const int gr   = lane >> 2;
    const int gc   = lane & 3;

    // staging: rows of 8 granules (16B each), swizzle s = g ^ (r&7)
    const int ar  = tid >> 1;           // 0..127
    const int ag0 = (tid & 1) * 4;      // 0 or 4
    const int br  = tid >> 2;           // 0..63
    const int bg0 = (tid & 3) * 2;      // 0,2,4,6

    uint32_t as_base = (uint32_t)__cvta_generic_to_shared(As);
    uint32_t bs_base = (uint32_t)__cvta_generic_to_shared(Bs);

    uint32_t adst[4], bdst[2];
    #pragma unroll
    for (int i = 0; i < 4; i++)
        adst[i] = (uint32_t)(ar*8 + ((ag0+i) ^ (ar & 7))) * 16u;
    #pragma unroll
    for (int j = 0; j < 2; j++)
        bdst[j] = (uint32_t)(br*8 + ((bg0+j) ^ (br & 7))) * 16u;

    const int nk = Kdim / BKh;

    #define ISSUE(T) do { \
        int _buf = (T) % STG; int _k0 = (T) * BKh; \
        uint32_t _ab = as_base + (uint32_t)(_buf*ASZh*2); \
        uint32_t _bb = bs_base + (uint32_t)(_buf*BSZh*2); \
        const __half* _arow = &A[(size_t)(m0 + ar)*Kdim + _k0]; \
        _Pragma("unroll") \
        for (int i = 0; i < 4; i++) cp16(_ab + adst[i], _arow + (ag0+i)*8); \
        const __half* _brow = &Bt[(size_t)(n0 + br)*Kdim + _k0]; \
        _Pragma("unroll") \
        for (int j = 0; j < 2; j++) cp16(_bb + bdst[j], _brow + (bg0+j)*8); \
    } while(0)

    // fragment lane roles
    const int a_ghi = lane >> 4;          // 0/1
    const int b_g   = lane >> 3;          // 0..3
    int a_m[2], b_n[4];
    #pragma unroll
    for (int mt = 0; mt < 2; mt++) a_m[mt] = wm*32 + mt*16 + (lane & 15);
    #pragma unroll
    for (int nt = 0; nt < 4; nt++) b_n[nt] = wn*32 + nt*8 + (lane & 7);

    float acc[2][4][4];
    #pragma unroll
    for (int i = 0; i < 2; i++)
        #pragma unroll
        for (int j = 0; j < 4; j++)
            #pragma unroll
            for (int q = 0; q < 4; q++) acc[i][j][q] = 0.f;

    ISSUE(0); cp_commit();
    ISSUE(1); cp_commit();
    ISSUE(2); cp_commit();

    for (int t = 0; t < nk; t++) {
        cp_wait<2>();
        __syncthreads();
        if (t + 3 < nk) ISSUE(t + 3);
        cp_commit();
        const uint32_t ab = as_base + (uint32_t)((t % STG)*ASZh*2);
        const uint32_t bb = bs_base + (uint32_t)((t % STG)*BSZh*2);

        uint32_t breg[4][8];
        #pragma unroll
        for (int nt = 0; nt < 4; nt++) {
            const int nr = b_n[nt];
            const int sw = nr & 7;
            ldsm4(&breg[nt][0], bb + (uint32_t)(nr*8 + ( b_g      ^ sw))*16u);
            ldsm4(&breg[nt][4], bb + (uint32_t)(nr*8 + ((b_g + 4) ^ sw))*16u);
        }
        #pragma unroll
        for (int ks = 0; ks < 4; ks++) {
            uint32_t areg[2][4];
            #pragma unroll
            for (int mt = 0; mt < 2; mt++) {
                const int mr = a_m[mt];
                ldsm4(areg[mt], ab + (uint32_t)(mr*8 + ((ks*2 + a_ghi) ^ (mr & 7)))*16u);
            }
            #pragma unroll
            for (int mt = 0; mt < 2; mt++)
                #pragma unroll
                for (int nt = 0; nt < 4; nt++)
                    mma_f16(acc[mt][nt], areg[mt], &breg[nt][ks >= 2 ? 4 + (ks-2)*2 : ks*2]);
        }
    }
    #undef ISSUE

    #pragma unroll
    for (int mt = 0; mt < 2; mt++) {
        #pragma unroll
        for (int nt = 0; nt < 4; nt++) {
            const int r0 = m0 + wm*32 + mt*16 + gr;
            const int c0 = n0 + wn*32 + nt*8 + gc*2;
            #pragma unroll
            for (int half = 0; half < 2; half++) {
                const int r = r0 + half*8;
                float v0 = acc[mt][nt][half*2 + 0];
                float v1 = acc[mt][nt][half*2 + 1];
                if (bias) { v0 += bias[c0]; v1 += bias[c0+1]; }
                if (GELU) {
                    v0 = 0.5f * v0 * (1.0f + erff(v0 * 0.70710678118654752f));
                    v1 = 0.5f * v1 * (1.0f + erff(v1 * 0.70710678118654752f));
                }
                if (res) {
                    v0 += res[(size_t)r*Ndim + c0];
                    v1 += res[(size_t)r*Ndim + c0 + 1];
                }
                if (OUTHALF)
                    *(__half2*)((__half*)Cm + (size_t)r*Ndim + c0) = __floats2half2_rn(v0, v1);
                else
                    *(float2*)((float*)Cm + (size_t)r*Ndim + c0) = make_float2(v0, v1);
            }
        }
    }
}

extern __shared__ unsigned char smem_raw[];

template<bool GELU, bool OUTHALF>
__global__ void __launch_bounds__(256, 2)
gemm_f16_k(const __half* __restrict__ A, const __half* __restrict__ Bt,
           const float* __restrict__ bias, const float* __restrict__ res,
           void* __restrict__ Cm, int Ndim, int Kdim){
    __half* As = (__half*)smem_raw;
    __half* Bs = As + STG*ASZh;
    gemm_body<GELU, OUTHALF>(As, Bs, A, Bt, bias, res, Cm, Ndim, Kdim,
                             blockIdx.y*BMh, blockIdx.x*BNh);
}

__global__ void __launch_bounds__(256, 2)
qkv_k(const __half* __restrict__ h,
      const __half* __restrict__ Wq, const __half* __restrict__ Wk, const __half* __restrict__ Wv,
      const float* __restrict__ bq, const float* __restrict__ bk, const float* __restrict__ bv,
      __half* __restrict__ q, __half* __restrict__ k, __half* __restrict__ v){
    __half* As = (__half*)smem_raw;
    __half* Bs = As + STG*ASZh;
    const __half* W  = (blockIdx.z == 0) ? Wq : (blockIdx.z == 1) ? Wk : Wv;
    const float*  bb = (blockIdx.z == 0) ? bq : (blockIdx.z == 1) ? bk : bv;
    __half*       o  = (blockIdx.z == 0) ? q  : (blockIdx.z == 1) ? k  : v;
    gemm_body<false, true>(As, Bs, h, W, bb, nullptr, o, Cz, Cz,
                           blockIdx.y*BMh, blockIdx.x*BNh);
}

// ---------------- fp32 SIMT GEMM (head only, B transposed) ----------------
__global__ void gemm_head_k(const float* __restrict__ A, const float* __restrict__ Bm,
                            float* __restrict__ Cm, int Ndim, int Kdim){
    __shared__ float As[64][17];
    __shared__ float Bs[16][64];
    int n0 = blockIdx.x * 64, m0 = blockIdx.y * 64;
    int tid = threadIdx.x;
    int tx = tid & 15, ty = tid >> 4;
    float acc[4][4] = {};
    for (int k0 = 0; k0 < Kdim; k0 += 16) {
        {
            int m = tid >> 2, kq = (tid & 3) * 4;
            float4 a4 = *(const float4*)&A[(size_t)(m0+m)*Kdim + k0 + kq];
            As[m][kq+0] = a4.x; As[m][kq+1] = a4.y; As[m][kq+2] = a4.z; As[m][kq+3] = a4.w;
        }
        {
            int n = tid >> 2, kq = (tid & 3) * 4;
            float4 b4 = *(const float4*)&Bm[(size_t)(n0+n)*Kdim + k0 + kq];
            Bs[kq+0][n] = b4.x; Bs[kq+1][n] = b4.y; Bs[kq+2][n] = b4.z; Bs[kq+3][n] = b4.w;
        }
        __syncthreads();
        #pragma unroll
        for (int kk = 0; kk < 16; kk++) {
            float a[4];
            #pragma unroll
            for (int i = 0; i < 4; i++) a[i] = As[ty*4+i][kk];
            float4 b4 = *(float4*)&Bs[kk][tx*4];
            float bb[4] = {b4.x, b4.y, b4.z, b4.w};
            #pragma unroll
            for (int i = 0; i < 4; i++)
                #pragma unroll
                for (int j = 0; j < 4; j++)
                    acc[i][j] = fmaf(a[i], bb[j], acc[i][j]);
        }
        __syncthreads();
    }
    #pragma unroll
    for (int i = 0; i < 4; i++) {
        int m = m0 + ty*4 + i;
        #pragma unroll
        for (int j = 0; j < 4; j++)
            Cm[(size_t)m*Ndim + n0 + tx*4 + j] = acc[i][j];
    }
}

// ============ fused attention fp16: 512 threads, ldmatrix (+trans for V) ============
#define SST 516
// S fp32 [64][SST] + Qs/Ps half [64][64] + Ks/Vs half 3x[64][64]
#define ATTF_SMEM (64*SST*4 + 64*64*2 + 3*64*64*2)

__global__ void __launch_bounds__(512, 1)
attn_fused_k(const __half* __restrict__ q, const __half* __restrict__ k,
             const __half* __restrict__ v, float* __restrict__ att,
             __half* __restrict__ y){
    float*  S  = (float*)smem_raw;             // [64][SST]
    __half* Qs = (__half*)(S + 64*SST);        // [64][64] swizzled (also Ps in phase 2)
    __half* Ks = Qs + 64*64;                   // 3 x [64][64] swizzled (also Vs)

    const int qb = gridDim.x - 1 - blockIdx.x; // heavy blocks first
    const int q0 = qb * 64;
    const int bh = blockIdx.y;
    const int b = bh / Hz, h = bh % Hz;
    const int tid  = threadIdx.x;
    const int lane = tid & 31;
    const int w    = tid >> 5;     // 0..15
    const int wm   = w >> 2;       // 0..3
    const int wn   = w & 3;        // 0..3
    const int gr   = lane >> 2;
    const int gc   = lane & 3;
    const int ntiles = qb + 1;

    uint32_t qs_base = (uint32_t)__cvta_generic_to_shared(Qs);
    uint32_t ks_base = (uint32_t)__cvta_generic_to_shared(Ks);

    // staging: 64 rows x 8 granules (16B), 512 threads -> 1 granule each
    const int lrow = tid >> 3;          // 0..63
    const int lg   = tid & 7;           // 0..7
    const uint32_t stg = (uint32_t)(lrow*8 + (lg ^ (lrow & 7))) * 16u;

    #define ISSUE_KT(T) \
        cp16(ks_base + (uint32_t)(((T) % 3) * 8192) + stg, \
             &k[((size_t)(b*Tz + (T)*64 + lrow))*Cz + h*HDz + lg*8])
    #define ISSUE_VT(T) \
        cp16(ks_base + (uint32_t)(((T) % 3) * 8192) + stg, \
             &v[((size_t)(b*Tz + (T)*64 + lrow))*Cz + h*HDz + lg*8])

    cp16(qs_base + stg, &q[((size_t)(b*Tz + q0 + lrow))*Cz + h*HDz + lg*8]);
    ISSUE_KT(0);
    cp_commit();
    if (ntiles > 1) ISSUE_KT(1);
    cp_commit();

    // fragment lane roles
    const int a_ghi = lane >> 4;                 // 0/1
    const int b_g   = lane >> 3;                 // 0..3
    const int am    = wm*16 + (lane & 15);
    const int asw   = am & 7;
    int b_n[2]; int bsw[2];
    #pragma unroll
    for (int nt = 0; nt < 2; nt++) {
        b_n[nt] = wn*16 + nt*8 + (lane & 7);
        bsw[nt] = b_n[nt] & 7;
    }

    // -------- phase 1: S = QK^T * scale --------
    for (int t = 0; t < ntiles; t++) {
        cp_wait<1>();
        __syncthreads();
        if (t + 2 < ntiles) ISSUE_KT(t + 2);
        cp_commit();
        const uint32_t kb = ks_base + (uint32_t)((t % 3) * 8192);

        uint32_t breg[2][8];
        #pragma unroll
        for (int nt = 0; nt < 2; nt++) {
            ldsm4(&breg[nt][0], kb + (uint32_t)(b_n[nt]*8 + ( b_g      ^ bsw[nt]))*16u);
            ldsm4(&breg[nt][4], kb + (uint32_t)(b_n[nt]*8 + ((b_g + 4) ^ bsw[nt]))*16u);
        }
        float acc[2][4] = {};
        #pragma unroll
        for (int ks = 0; ks < 4; ks++) {
            uint32_t areg[4];
            ldsm4(areg, qs_base + (uint32_t)(am*8 + ((ks*2 + a_ghi) ^ asw))*16u);
            const int bo = (ks >= 2) ? 4 + (ks-2)*2 : ks*2;
            mma_f16(acc[0], areg, &breg[0][bo]);
            mma_f16(acc[1], areg, &breg[1][bo]);
        }
        const int kt0 = t * 64;
        #pragma unroll
        for (int nt = 0; nt < 2; nt++) {
            const int r = wm*16 + gr;
            const int c = kt0 + wn*16 + nt*8 + gc*2;
            *(float2*)&S[ r     *SST + c] = make_float2(acc[nt][0]*0.125f, acc[nt][1]*0.125f);
            *(float2*)&S[(r + 8)*SST + c] = make_float2(acc[nt][2]*0.125f, acc[nt][3]*0.125f);
        }
    }
    __syncthreads();

    // -------- softmax (warp per row): att <- p fp32; S keeps p fp32 --------
    const int kmax = q0 + 64;
    for (int r = w; r < 64; r += 16) {
        const int qt = q0 + r;
        float* Sr = &S[r*SST];
        float mx = -3.0e38f;
        for (int kt = lane; kt < kmax; kt += 32) {
            float s = Sr[kt];
            if (kt <= qt) mx = fmaxf(mx, s);
        }
        mx = warp_max(mx);
        float sum = 0.f;
        for (int kt = lane; kt < kmax; kt += 32) {
            float e = (kt <= qt) ? __expf(Sr[kt] - mx) : 0.f;
            Sr[kt] = e;
            sum += e;
        }
        sum = warp_sum(sum);
        const float inv = 1.0f / sum;
        float* orow = att + ((size_t)bh*Tz + qt)*Tz;
        for (int kt = lane; kt < kmax; kt += 32) {
            float p = Sr[kt] * inv;
            Sr[kt] = p;
            orow[kt] = p;
        }
        for (int kt = kmax + lane; kt < Tz; kt += 32) orow[kt] = 0.f;
    }
    __syncthreads();

    // -------- phase 2: y = P @ V  (Vs = Ks bufs via cp.async; Ps = Qs) --------
    ISSUE_VT(0); cp_commit();
    if (ntiles > 1) { ISSUE_VT(1); } cp_commit();

    // Ps conversion roles: row = tid&63, granule = tid>>6
    const int pr = tid & 63;
    const int pg = tid >> 6;          // 0..7
    const uint32_t pst = (uint32_t)(pr*8 + (pg ^ (pr & 7))) * 16u;

    float acc2[2][4] = {};

    for (int t = 0; t < ntiles; t++) {
        cp_wait<1>();
        __syncthreads();                       // V(t) ready; all prior compute done
        if (t + 2 < ntiles) ISSUE_VT(t + 2);
        cp_commit();
        // convert P tile (fp32 S -> fp16 Ps in Qs buffer)
        {
            const float* sp = &S[pr*SST + t*64 + pg*8];
            uint4 val;
            val.x = h2u(__floats2half2_rn(sp[0], sp[1]));
            val.y = h2u(__floats2half2_rn(sp[2], sp[3]));
            val.z = h2u(__floats2half2_rn(sp[4], sp[5]));
            val.w = h2u(__floats2half2_rn(sp[6], sp[7]));
            *(uint4*)((char*)Qs + pst) = val;
        }
        __syncthreads();
        const uint32_t vb = ks_base + (uint32_t)((t % 3) * 8192);

        uint32_t breg[2][8];
        #pragma unroll
        for (int nt = 0; nt < 2; nt++) {
            const int dgr = wn*2 + nt;         // d granule 0..7
            const int r0 = lane;               // rows 0..31
            const int r1 = 32 + lane;
            ldsm4t(&breg[nt][0], vb + (uint32_t)(r0*8 + (dgr ^ (r0 & 7)))*16u);
            ldsm4t(&breg[nt][4], vb + (uint32_t)(r1*8 + (dgr ^ (r1 & 7)))*16u);
        }
        #pragma unroll
        for (int ks = 0; ks < 4; ks++) {
            uint32_t areg[4];
            ldsm4(areg, qs_base + (uint32_t)(am*8 + ((ks*2 + a_ghi) ^ asw))*16u);
            const int bo = (ks >= 2) ? 4 + (ks-2)*2 : ks*2;
            mma_f16(acc2[0], areg, &breg[0][bo]);
            mma_f16(acc2[1], areg, &breg[1][bo]);
        }
    }

    // write y (half, fused transpose into [B,T,C])
    __half* Cp = (__half*)y + ((size_t)(b*Tz + q0))*Cz + h*HDz;
    #pragma unroll
    for (int nt = 0; nt < 2; nt++) {
        const int r = wm*16 + gr;
        const int c = wn*16 + nt*8 + gc*2;
        *(__half2*)&Cp[(size_t) r     *Cz + c] = __floats2half2_rn(acc2[nt][0], acc2[nt][1]);
        *(__half2*)&Cp[(size_t)(r + 8)*Cz + c] = __floats2half2_rn(acc2[nt][2], acc2[nt][3]);
    }
    #undef ISSUE_KT
    #undef ISSUE_VT
}

// ---------------- host launch ----------------
extern "C" void kernel_launch(void* const* d_in, const int* in_sizes, int n_in,
                              void* d_out, int out_size){
    const int*   idx    = (const int*)  d_in[0];
    const float* tok    = (const float*)d_in[1];
    const float* typ    = (const float*)d_in[2];
    const float* pos    = (const float*)d_in[3];
    const float* Wq     = (const float*)d_in[4];
    const float* bq     = (const float*)d_in[5];
    const float* Wk     = (const float*)d_in[6];
    const float* bk     = (const float*)d_in[7];
    const float* Wv     = (const float*)d_in[8];
    const float* bv     = (const float*)d_in[9];
    const float* Wp     = (const float*)d_in[10];
    const float* bp     = (const float*)d_in[11];
    const float* ln1_w  = (const float*)d_in[12];
    const float* ln1_b  = (const float*)d_in[13];
    const float* ln2_w  = (const float*)d_in[14];
    const float* ln2_b  = (const float*)d_in[15];
    const float* W1     = (const float*)d_in[16];
    const float* b1     = (const float*)d_in[17];
    const float* W2     = (const float*)d_in[18];
    const float* b2     = (const float*)d_in[19];
    const float* lnf_w  = (const float*)d_in[20];
    const float* lnf_b  = (const float*)d_in[21];
    const float* head_w = (const float*)d_in[22];

    float* out        = (float*)d_out;
    float* out_logits = out;
    float* out_x      = out + (size_t)Mz*Vz;
    float* out_att    = out_x + (size_t)Mz*Cz;

    float  *px;
    __half *ph, *pq, *pk, *pv, *py, *pff;
    __half *pwq, *pwk, *pwv, *pwp, *pw1, *pw2;
    cudaGetSymbolAddress((void**)&px,  g_x);
    cudaGetSymbolAddress((void**)&ph,  g_h);
    cudaGetSymbolAddress((void**)&pq,  g_q);
    cudaGetSymbolAddress((void**)&pk,  g_k);
    cudaGetSymbolAddress((void**)&pv,  g_v);
    cudaGetSymbolAddress((void**)&py,  g_y);
    cudaGetSymbolAddress((void**)&pff, g_ff);
    cudaGetSymbolAddress((void**)&pwq, g_wq);
    cudaGetSymbolAddress((void**)&pwk, g_wk);
    cudaGetSymbolAddress((void**)&pwv, g_wv);
    cudaGetSymbolAddress((void**)&pwp, g_wp);
    cudaGetSymbolAddress((void**)&pw1, g_w1);
    cudaGetSymbolAddress((void**)&pw2, g_w2);

    static bool attrs_set = false;
    if (!attrs_set) {
        cudaFuncSetAttribute((const void*)gemm_f16_k<false,false>, cudaFuncAttributeMaxDynamicSharedMemorySize, GEMM_SMEM);
        cudaFuncSetAttribute((const void*)gemm_f16_k<true,true>,   cudaFuncAttributeMaxDynamicSharedMemorySize, GEMM_SMEM);
        cudaFuncSetAttribute((const void*)qkv_k,                   cudaFuncAttributeMaxDynamicSharedMemorySize, GEMM_SMEM);
        cudaFuncSetAttribute((const void*)attn_fused_k,            cudaFuncAttributeMaxDynamicSharedMemorySize, ATTF_SMEM);
        attrs_set = true;
    }

    dim3 tb(32, 8);
    wtrans_k<<<dim3(Cz/32,  Cz/32,  Lz), tb>>>(Wq, pwq, Cz, Cz);
    wtrans_k<<<dim3(Cz/32,  Cz/32,  Lz), tb>>>(Wk, pwk, Cz, Cz);
    wtrans_k<<<dim3(Cz/32,  Cz/32,  Lz), tb>>>(Wv, pwv, Cz, Cz);
    wtrans_k<<<dim3(Cz/32,  Cz/32,  Lz), tb>>>(Wp, pwp, Cz, Cz);
    wtrans_k<<<dim3(FFz/32, Cz/32,  Lz), tb>>>(W1, pw1, Cz, FFz);
    wtrans_k<<<dim3(Cz/32,  FFz/32, Lz), tb>>>(W2, pw2, FFz, Cz);

    embed_k<<<(Mz*Cz + 255)/256, 256>>>(idx, tok, typ, pos, px);

    dim3 gQKV3(Cz/BNh, Mz/BMh, 3);
    dim3 gP(Cz/BNh,  Mz/BMh);
    dim3 gFF1(FFz/BNh, Mz/BMh);
    dim3 gHead(Vz/64, Mz/64);
    dim3 gAtt(Tz/64, Bz*Hz);

    for (int l = 0; l < Lz; l++) {
        float* attL = out_att + (size_t)l*Bz*Hz*Tz*Tz;

        ln_k<true><<<Mz/8, 256>>>(px, ln1_w + (size_t)l*Cz, ln1_b + (size_t)l*Cz, ph);
        qkv_k<<<gQKV3, 256, GEMM_SMEM>>>(ph,
            pwq + (size_t)l*Cz*Cz, pwk + (size_t)l*Cz*Cz, pwv + (size_t)l*Cz*Cz,
            bq + (size_t)l*Cz, bk + (size_t)l*Cz, bv + (size_t)l*Cz,
            pq, pk, pv);
        attn_fused_k<<<gAtt, 512, ATTF_SMEM>>>(pq, pk, pv, attL, py);
        gemm_f16_k<false,false><<<gP, 256, GEMM_SMEM>>>(py, pwp + (size_t)l*Cz*Cz,
            bp + (size_t)l*Cz, px, px, Cz, Cz);
        ln_k<true><<<Mz/8, 256>>>(px, ln2_w + (size_t)l*Cz, ln2_b + (size_t)l*Cz, ph);
        gemm_f16_k<true,true><<<gFF1, 256, GEMM_SMEM>>>(ph, pw1 + (size_t)l*Cz*FFz,
            b1 + (size_t)l*FFz, nullptr, pff, FFz, Cz);
        gemm_f16_k<false,false><<<gP, 256, GEMM_SMEM>>>(pff, pw2 + (size_t)l*FFz*Cz,
            b2 + (size_t)l*Cz, px, px, Cz, FFz);
    }

    ln_k<false><<<Mz/8, 256>>>(px, lnf_w, lnf_b, out_x);
    gemm_head_k<<<gHead, 256>>>(out_x, head_w, out_logits, Vz, Cz);
}